// round 13
// baseline (speedup 1.0000x reference)
#include <cuda_runtime.h>
#include <cuda_fp16.h>
#include <math.h>
#include <stdint.h>

// Problem constants
#define DIMM   768
#define NHEADS 12
#define HDIM   64
#define MLPD   3072
#define NDEPTH 12
#define BATCH  16
#define SEQ    512
#define MROWS  (BATCH*SEQ)    // 8192
#define NZ     (BATCH*NHEADS) // 192
#define QKVN   (3*DIMM)       // 2304

// ---------------- scratch (static device, no allocation) ----------------
__device__ float  g_x  [(size_t)MROWS*DIMM];
__device__ float  g_x2 [(size_t)MROWS*DIMM];
__device__ float  g_bqkv[QKVN];
__device__ __half h_ln [(size_t)MROWS*DIMM];
__device__ __half h_qkv[(size_t)MROWS*QKVN];
__device__ __half h_hid[(size_t)MROWS*MLPD];
__device__ __half h_wqkvT[(size_t)QKVN*DIMM];      // [2304,768] fp16, [N,K]
__device__ __half h_w1T [(size_t)MLPD*DIMM];
__device__ __half h_w2T [(size_t)DIMM*MLPD];

// ---------------- helpers ----------------
__device__ __forceinline__ float gelu_exact(float v){
    return 0.5f * v * (1.0f + erff(v * 0.70710678118654752440f));
}
__device__ __forceinline__ uint32_t smem_u32(const void* p){
    uint32_t a;
    asm("{ .reg .u64 t; cvta.to.shared.u64 t, %1; cvt.u32.u64 %0, t; }" : "=r"(a) : "l"(p));
    return a;
}
__device__ __forceinline__ void cpa16(uint32_t s, const void* g){
    asm volatile("cp.async.cg.shared.global [%0], [%1], 16;" :: "r"(s), "l"(g));
}
__device__ __forceinline__ void cpa_commit(){ asm volatile("cp.async.commit_group;" ::: "memory"); }
template<int N> __device__ __forceinline__ void cpa_wait(){
    asm volatile("cp.async.wait_group %0;" :: "n"(N) : "memory");
}
__device__ __forceinline__ void ldsm4(uint32_t* r, uint32_t addr){
    asm volatile("ldmatrix.sync.aligned.m8n8.x4.shared.b16 {%0,%1,%2,%3}, [%4];"
        : "=r"(r[0]), "=r"(r[1]), "=r"(r[2]), "=r"(r[3]) : "r"(addr));
}
__device__ __forceinline__ void ldsm4t(uint32_t* r, uint32_t addr){
    asm volatile("ldmatrix.sync.aligned.m8n8.x4.trans.shared.b16 {%0,%1,%2,%3}, [%4];"
        : "=r"(r[0]), "=r"(r[1]), "=r"(r[2]), "=r"(r[3]) : "r"(addr));
}
__device__ __forceinline__ void mma_f16(float* d, const uint32_t* a, const uint32_t* b){
    asm volatile(
        "mma.sync.aligned.m16n8k16.row.col.f32.f16.f16.f32 "
        "{%0,%1,%2,%3}, {%4,%5,%6,%7}, {%8,%9}, {%0,%1,%2,%3};\n"
        : "+f"(d[0]), "+f"(d[1]), "+f"(d[2]), "+f"(d[3])
        : "r"(a[0]), "r"(a[1]), "r"(a[2]), "r"(a[3]), "r"(b[0]), "r"(b[1]));
}
__device__ __forceinline__ uint32_t packh2(float x, float y){
    __half2 h = __floats2half2_rn(x, y);
    return *(uint32_t*)&h;
}

// =========================================================================
// fp16 GEMM, fp32 accumulate — BK=64 (round-12 winner), BN templated:
//   C[M,N] = A[M,K](row, K contig, half) * B[N,K]^T (row, K contig, half)
//   CTA 128xBN (BN in {128,64}), BK=64, S=3 stages, 2 CTAs/SM,
//   8 warps as 2(m) x 4(n), warp tile 64 x BN/4, 4 ks-steps per k-tile.
//   BN=64 halves per-tile cost for skinny-N GEMMs (MLP2 wave quantization).
// Smem: rows of 128B (64 halves), 16B unit u in 0..7, swizzle u ^ (row&7).
// EPI bits: 1=+bias, 2=gelu, 4=+residual(fp32), 32=half out (else fp32)
// =========================================================================
struct PH {
    const __half* A; const __half* B; void* C;
    const float* bias; const float* R;
    int lda, ldb, ldc, ldr;
    int nk;         // K / 64
};

template<int BN, int EPI>
__global__ __launch_bounds__(256, 2) void gemmh(PH p){
    constexpr int S = 3;
    constexpr int ABYTES = 128*128;           // 16384
    constexpr int BBYTES = BN*128;
    constexpr int STAGE  = ABYTES + BBYTES;
    constexpr int WTN = BN/4;                 // warp n-extent
    constexpr int NT = WTN/8, MT = 4;
    constexpr int BIT = BN/32;                // B cp.async iters (256 thr)

    extern __shared__ char sm[];
    const uint32_t smb = smem_u32(sm);
    const int tid  = threadIdx.x;
    const int lane = tid & 31;
    const int warp = tid >> 5;
    const int wm   = warp >> 2;
    const int wn   = warp & 3;

    const __half* Ag = p.A + (long)blockIdx.y * 128 * p.lda;
    const __half* Bg = p.B + (long)blockIdx.x * BN * p.ldb;

    float acc[MT][NT][4];
    #pragma unroll
    for(int i=0;i<MT;i++)
        #pragma unroll
        for(int j=0;j<NT;j++){
            acc[i][j][0]=0.f; acc[i][j][1]=0.f; acc[i][j][2]=0.f; acc[i][j][3]=0.f;
        }

    auto load_stage = [&](int kt, int s){
        const uint32_t ab = smb + s*STAGE;
        #pragma unroll
        for(int t=0;t<4;t++){
            int i = tid + t*256, row = i>>3;
            uint32_t u = (uint32_t)(i&7);
            cpa16(ab + (uint32_t)row*128 + (u ^ ((uint32_t)row&7))*16,
                  Ag + (long)row*p.lda + kt*64 + u*8);
        }
        const uint32_t bb = ab + ABYTES;
        #pragma unroll
        for(int t=0;t<BIT;t++){
            int i = tid + t*256, row = i>>3;
            uint32_t u = (uint32_t)(i&7);
            cpa16(bb + (uint32_t)row*128 + (u ^ ((uint32_t)row&7))*16,
                  Bg + (long)row*p.ldb + kt*64 + u*8);
        }
    };

    const int nk = p.nk;
    #pragma unroll
    for(int s=0;s<S-1;s++){
        if(s < nk) load_stage(s, s);
        cpa_commit();
    }

    int stg = 0;
    for(int kt = 0; kt < nk; kt++){
        cpa_wait<S-2>();
        __syncthreads();
        const uint32_t ab = smb + stg*STAGE;
        const uint32_t bb = ab + ABYTES;

        #pragma unroll
        for(int ks=0; ks<4; ks++){
            uint32_t af[MT][4], bf[NT][2];
            #pragma unroll
            for(int mt=0; mt<MT; mt++){
                uint32_t row = (uint32_t)(wm*64 + mt*16 + ((lane>>3)&1)*8 + (lane&7));
                uint32_t u   = (uint32_t)(ks*2 + (lane>>4));
                ldsm4(af[mt], ab + row*128 + (u ^ (row&7))*16);
            }
            #pragma unroll
            for(int j=0; j<NT/2; j++){
                uint32_t n = (uint32_t)(wn*WTN + j*16 + ((lane>>4)&1)*8 + (lane&7));
                uint32_t u = (uint32_t)(ks*2 + ((lane>>3)&1));
                uint32_t r4[4];
                ldsm4(r4, bb + n*128 + (u ^ (n&7))*16);
                bf[2*j][0]=r4[0]; bf[2*j][1]=r4[1]; bf[2*j+1][0]=r4[2]; bf[2*j+1][1]=r4[3];
            }
            #pragma unroll
            for(int mt=0; mt<MT; mt++)
                #pragma unroll
                for(int nt=0; nt<NT; nt++)
                    mma_f16(acc[mt][nt], af[mt], bf[nt]);
        }

        const int nx = kt + S - 1;
        if(nx < nk){
            int ns = stg + (S-1); if(ns >= S) ns -= S;
            load_stage(nx, ns);
        }
        cpa_commit();
        if(++stg == S) stg = 0;
    }

    // ---------------- epilogue ----------------
    const long crow0 = (long)blockIdx.y*128*p.ldc + (long)blockIdx.x*BN;
    const float* Rg = nullptr;
    if(EPI & 4)
        Rg = p.R + (long)blockIdx.y*128*p.ldr + (long)blockIdx.x*BN;

    #pragma unroll
    for(int mt=0; mt<MT; mt++){
        #pragma unroll
        for(int nt=0; nt<NT; nt++){
            const int col = wn*WTN + nt*8 + 2*(lane&3);
            #pragma unroll
            for(int hh=0; hh<2; hh++){
                const int row = wm*64 + mt*16 + (lane>>2) + hh*8;
                float v0 = acc[mt][nt][hh*2], v1 = acc[mt][nt][hh*2+1];
                if(EPI & 1){
                    float2 bb = *(const float2*)&p.bias[blockIdx.x*BN + col];
                    v0 += bb.x; v1 += bb.y;
                }
                if(EPI & 2){ v0 = gelu_exact(v0); v1 = gelu_exact(v1); }
                if(EPI & 4){
                    float2 rv = *(const float2*)(Rg + (long)row*p.ldr + col);
                    v0 += rv.x; v1 += rv.y;
                }
                if(EPI & 32){
                    __half2* Ch = (__half2*)((__half*)p.C + crow0 + (long)row*p.ldc + col);
                    *Ch = __floats2half2_rn(v0, v1);
                }else{
                    float* Cf = (float*)p.C + crow0 + (long)row*p.ldc + col;
                    *(float2*)Cf = make_float2(v0, v1);
                }
            }
        }
    }
}

// =========================================================================
// Fused flash attention: out = softmax(Q K^T / 8) V + xres   (round-6, unchanged)
// =========================================================================
__global__ __launch_bounds__(256, 1) void flash(
    const __half* __restrict__ qkv, const float* __restrict__ xres,
    float* __restrict__ out)
{
    extern __shared__ char sm[];
    const uint32_t smb = smem_u32(sm);
    const uint32_t qs  = smb;
    const int tid = threadIdx.x, lane = tid & 31, warp = tid >> 5;
    const int z = blockIdx.y, zb = z / NHEADS, zh = z % NHEADS;
    const long grow0 = (long)zb*SEQ + (long)blockIdx.x*128;

    const __half* Qg = qkv + grow0*QKVN + zh*HDIM;
    const __half* Kg = qkv + (long)zb*SEQ*QKVN + DIMM   + zh*HDIM;
    const __half* Vg = qkv + (long)zb*SEQ*QKVN + 2*DIMM + zh*HDIM;

    auto ldtile = [&](uint32_t dst, const __half* src){
        #pragma unroll
        for(int t=0;t<4;t++){
            int i = tid + t*256, row = i>>3;
            uint32_t u = (uint32_t)(i&7);
            cpa16(dst + (uint32_t)row*128 + (u ^ ((uint32_t)row&7))*16,
                  src + (long)row*QKVN + u*8);
        }
    };

    ldtile(qs, Qg);                                                       cpa_commit();
    ldtile(smb+16384, Kg);             ldtile(smb+32768, Vg);             cpa_commit();
    ldtile(smb+49152, Kg + 128l*QKVN); ldtile(smb+65536, Vg + 128l*QKVN); cpa_commit();

    cpa_wait<2>();
    __syncthreads();

    uint32_t qf[4][4];
    #pragma unroll
    for(int ks=0; ks<4; ks++){
        uint32_t row = (uint32_t)(warp*16 + ((lane>>3)&1)*8 + (lane&7));
        uint32_t u   = (uint32_t)(2*ks + (lane>>4));
        ldsm4(qf[ks], qs + row*128 + (u ^ (row&7))*16);
    }

    float m0 = -1e30f, m1 = -1e30f, l0 = 0.f, l1 = 0.f;
    float o[8][4];
    #pragma unroll
    for(int nt=0;nt<8;nt++){ o[nt][0]=0.f; o[nt][1]=0.f; o[nt][2]=0.f; o[nt][3]=0.f; }

    for(int kb=0; kb<4; kb++){
        if(kb < 2) cpa_wait<1>(); else cpa_wait<0>();
        __syncthreads();
        const uint32_t kbuf = smb + 16384 + (uint32_t)(kb&1)*32768;
        const uint32_t vbuf = kbuf + 16384;

        float s[16][4];
        #pragma unroll
        for(int nt=0;nt<16;nt++){ s[nt][0]=0.f; s[nt][1]=0.f; s[nt][2]=0.f; s[nt][3]=0.f; }
        #pragma unroll
        for(int ks=0; ks<4; ks++){
            uint32_t bf[16][2];
            #pragma unroll
            for(int j=0;j<8;j++){
                uint32_t n = (uint32_t)(j*16 + ((lane>>4)&1)*8 + (lane&7));
                uint32_t u = (uint32_t)(2*ks + ((lane>>3)&1));
                uint32_t r4[4];
                ldsm4(r4, kbuf + n*128 + (u ^ (n&7))*16);
                bf[2*j][0]=r4[0]; bf[2*j][1]=r4[1]; bf[2*j+1][0]=r4[2]; bf[2*j+1][1]=r4[3];
            }
            #pragma unroll
            for(int nt=0;nt<16;nt++) mma_f16(s[nt], qf[ks], bf[nt]);
        }

        float cm0 = -1e30f, cm1 = -1e30f;
        #pragma unroll
        for(int nt=0;nt<16;nt++){
            s[nt][0]*=0.125f; s[nt][1]*=0.125f; s[nt][2]*=0.125f; s[nt][3]*=0.125f;
            cm0 = fmaxf(cm0, fmaxf(s[nt][0], s[nt][1]));
            cm1 = fmaxf(cm1, fmaxf(s[nt][2], s[nt][3]));
        }
        cm0 = fmaxf(cm0, __shfl_xor_sync(~0u,cm0,1));
        cm0 = fmaxf(cm0, __shfl_xor_sync(~0u,cm0,2));
        cm1 = fmaxf(cm1, __shfl_xor_sync(~0u,cm1,1));
        cm1 = fmaxf(cm1, __shfl_xor_sync(~0u,cm1,2));
        const float mn0 = fmaxf(m0, cm0), mn1 = fmaxf(m1, cm1);
        const float sf0 = __expf(m0 - mn0), sf1 = __expf(m1 - mn1);
        float sum0 = 0.f, sum1 = 0.f;
        #pragma unroll
        for(int nt=0;nt<16;nt++){
            s[nt][0] = __expf(s[nt][0]-mn0); s[nt][1] = __expf(s[nt][1]-mn0);
            s[nt][2] = __expf(s[nt][2]-mn1); s[nt][3] = __expf(s[nt][3]-mn1);
            sum0 += s[nt][0] + s[nt][1];
            sum1 += s[nt][2] + s[nt][3];
        }
        sum0 += __shfl_xor_sync(~0u,sum0,1); sum0 += __shfl_xor_sync(~0u,sum0,2);
        sum1 += __shfl_xor_sync(~0u,sum1,1); sum1 += __shfl_xor_sync(~0u,sum1,2);
        l0 = l0*sf0 + sum0; l1 = l1*sf1 + sum1;
        m0 = mn0; m1 = mn1;
        #pragma unroll
        for(int nt=0;nt<8;nt++){
            o[nt][0]*=sf0; o[nt][1]*=sf0; o[nt][2]*=sf1; o[nt][3]*=sf1;
        }

        #pragma unroll
        for(int kk=0; kk<8; kk++){
            uint32_t pa[4];
            pa[0] = packh2(s[2*kk  ][0], s[2*kk  ][1]);
            pa[1] = packh2(s[2*kk  ][2], s[2*kk  ][3]);
            pa[2] = packh2(s[2*kk+1][0], s[2*kk+1][1]);
            pa[3] = packh2(s[2*kk+1][2], s[2*kk+1][3]);
            uint32_t bf[8][2];
            const int g = lane>>3, i = lane&7;
            #pragma unroll
            for(int dp=0; dp<4; dp++){
                uint32_t key = (uint32_t)(kk*16 + (g&1)*8 + i);
                uint32_t dg  = (uint32_t)(dp*2 + (g>>1));
                uint32_t r4[4];
                ldsm4t(r4, vbuf + key*128 + (dg ^ (key&7))*16);
                bf[2*dp][0]=r4[0]; bf[2*dp][1]=r4[1]; bf[2*dp+1][0]=r4[2]; bf[2*dp+1][1]=r4[3];
            }
            #pragma unroll
            for(int nt=0;nt<8;nt++) mma_f16(o[nt], pa, bf[nt]);
        }

        __syncthreads();
        if(kb + 2 < 4){
            ldtile(smb+16384+(uint32_t)(kb&1)*32768, Kg + (long)(kb+2)*128*QKVN);
            ldtile(smb+32768+(uint32_t)(kb&1)*32768, Vg + (long)(kb+2)*128*QKVN);
            cpa_commit();
        }
    }

    const float inv0 = 1.f/l0, inv1 = 1.f/l1;
    const long gr0 = grow0 + warp*16 + (lane>>2);
    const long gr1 = gr0 + 8;
    const int  col = zh*HDIM + 2*(lane&3);
    #pragma unroll
    for(int nt=0; nt<8; nt++){
        const int c = col + nt*8;
        float2 r0 = *(const float2*)&xres[gr0*DIMM + c];
        float2 r1 = *(const float2*)&xres[gr1*DIMM + c];
        *(float2*)&out[gr0*DIMM + c] = make_float2(o[nt][0]*inv0 + r0.x, o[nt][1]*inv0 + r0.y);
        *(float2*)&out[gr1*DIMM + c] = make_float2(o[nt][2]*inv1 + r1.x, o[nt][3]*inv1 + r1.y);
    }
}

// ---------------- LayerNorm, warp-per-row (round-9, unchanged) -----------------
__global__ __launch_bounds__(256) void ln_kernel(
    const float* __restrict__ x, const float* __restrict__ w,
    const float* __restrict__ b, __half* __restrict__ out)
{
    const int warp = threadIdx.x >> 5, lane = threadIdx.x & 31;
    const long row = (long)blockIdx.x*8 + warp;
    const float4* xr = (const float4*)(x + row*DIMM);

    float4 v[6];
    #pragma unroll
    for(int i=0;i<6;i++) v[i] = xr[lane + i*32];

    float s = 0.f, s2 = 0.f;
    #pragma unroll
    for(int i=0;i<6;i++){
        s  += (v[i].x + v[i].y) + (v[i].z + v[i].w);
        s2 += v[i].x*v[i].x + v[i].y*v[i].y + v[i].z*v[i].z + v[i].w*v[i].w;
    }
    #pragma unroll
    for(int o=16;o;o>>=1){
        s  += __shfl_xor_sync(~0u, s,  o);
        s2 += __shfl_xor_sync(~0u, s2, o);
    }
    const float mu  = s * (1.f/DIMM);
    const float var = s2 * (1.f/DIMM) - mu*mu;
    const float inv = rsqrtf(var + 1e-5f);

    const float4* wv = (const float4*)w;
    const float4* bv = (const float4*)b;
    uint2* orow = (uint2*)(out + row*DIMM);
    #pragma unroll
    for(int i=0;i<6;i++){
        const int c = lane + i*32;
        float4 ww = wv[c], bb = bv[c];
        uint2 pk;
        pk.x = packh2((v[i].x - mu)*inv*ww.x + bb.x, (v[i].y - mu)*inv*ww.y + bb.y);
        pk.y = packh2((v[i].z - mu)*inv*ww.z + bb.z, (v[i].w - mu)*inv*ww.w + bb.w);
        orow[c] = pk;
    }
}

// ---------------- weight transpose [K,N] fp32 -> [N,K] fp16 --------------------
__global__ void wtrans(const float* __restrict__ in, __half* __restrict__ out, int K, int N){
    __shared__ float t[32][33];
    const int k0 = blockIdx.y*32, n0 = blockIdx.x*32;
    const int tx = threadIdx.x & 31, ty = threadIdx.x >> 5;
    #pragma unroll
    for(int i=0;i<4;i++)
        t[ty+8*i][tx] = in[(size_t)(k0+ty+8*i)*N + n0+tx];
    __syncthreads();
    #pragma unroll
    for(int i=0;i<4;i++)
        out[(size_t)(n0+ty+8*i)*K + k0+tx] = __float2half_rn(t[tx][ty+8*i]);
}

__global__ void concat_bias(const float* a, const float* b, const float* c, float* o){
    int i = blockIdx.x*256 + threadIdx.x;
    if(i < DIMM){ o[i] = a[i]; o[i+DIMM] = b[i]; o[i+2*DIMM] = c[i]; }
}

// ---------------- host ----------------
static PH mkph(const __half* A, const __half* B, void* C, const float* bias,
               const float* R, int lda, int ldb, int ldc, int ldr, int nk){
    PH p{};
    p.A=A; p.B=B; p.C=C; p.bias=bias; p.R=R;
    p.lda=lda; p.ldb=ldb; p.ldc=ldc; p.ldr=ldr;
    p.nk=nk;
    return p;
}

extern "C" void kernel_launch(void* const* d_in, const int* in_sizes, int n_in,
                              void* d_out, int out_size){
    const float* x    = (const float*)d_in[0];
    const float* ln_w = (const float*)d_in[1];
    const float* ln_b = (const float*)d_in[2];
    const float* wq   = (const float*)d_in[3];
    const float* bq   = (const float*)d_in[4];
    const float* wk   = (const float*)d_in[5];
    const float* bk   = (const float*)d_in[6];
    const float* wv   = (const float*)d_in[7];
    const float* bv   = (const float*)d_in[8];
    const float* w1   = (const float*)d_in[9];
    const float* b1   = (const float*)d_in[10];
    const float* w2   = (const float*)d_in[11];
    const float* b2   = (const float*)d_in[12];

    float *px, *px2, *pbqkv;
    __half *pln, *pqkv, *phid, *pwqkvT, *pw1T, *pw2T;
    cudaGetSymbolAddress((void**)&px    , g_x   );
    cudaGetSymbolAddress((void**)&px2   , g_x2  );
    cudaGetSymbolAddress((void**)&pbqkv , g_bqkv);
    cudaGetSymbolAddress((void**)&pln   , h_ln  );
    cudaGetSymbolAddress((void**)&pqkv  , h_qkv );
    cudaGetSymbolAddress((void**)&phid  , h_hid );
    cudaGetSymbolAddress((void**)&pwqkvT, h_wqkvT);
    cudaGetSymbolAddress((void**)&pw1T  , h_w1T );
    cudaGetSymbolAddress((void**)&pw2T  , h_w2T );

    const int SMG128 = 3*32768;              // 98304  (2 CTAs/SM = 192KB)
    const int SMG64  = 3*(16384 + 8192);     // 73728
    const int SMFL   = 16384 + 2*32768;      // 81920
    cudaFuncSetAttribute(gemmh<128,33>, cudaFuncAttributeMaxDynamicSharedMemorySize, SMG128);
    cudaFuncSetAttribute(gemmh<128,35>, cudaFuncAttributeMaxDynamicSharedMemorySize, SMG128);
    cudaFuncSetAttribute(gemmh< 64, 5>, cudaFuncAttributeMaxDynamicSharedMemorySize, SMG64);
    cudaFuncSetAttribute(flash,         cudaFuncAttributeMaxDynamicSharedMemorySize, SMFL);

    // weight prep (amortized over 12 layers)
    wtrans<<<dim3(DIMM/32, DIMM/32), 256>>>(wq, pwqkvT,                       DIMM, DIMM);
    wtrans<<<dim3(DIMM/32, DIMM/32), 256>>>(wk, pwqkvT + (size_t)DIMM*DIMM,   DIMM, DIMM);
    wtrans<<<dim3(DIMM/32, DIMM/32), 256>>>(wv, pwqkvT + (size_t)2*DIMM*DIMM, DIMM, DIMM);
    wtrans<<<dim3(MLPD/32, DIMM/32), 256>>>(w1, pw1T, DIMM, MLPD);
    wtrans<<<dim3(DIMM/32, MLPD/32), 256>>>(w2, pw2T, MLPD, DIMM);
    concat_bias<<<3, 256>>>(bq, bk, bv, pbqkv);

    cudaMemcpyAsync(px, x, (size_t)MROWS*DIMM*sizeof(float), cudaMemcpyDeviceToDevice);

    for(int l=0; l<NDEPTH; l++){
        // --- attention block ---
        ln_kernel<<<MROWS/8, 256>>>(px, ln_w, ln_b, pln);

        // fused QKV: [8192,2304] ; bias, half out
        { PH p = mkph(pln, pwqkvT, pqkv, pbqkv, nullptr, DIMM, DIMM, QKVN, 0, DIMM/64);
          gemmh<128,33><<<dim3(QKVN/128, MROWS/128, 1), 256, SMG128>>>(p); }

        // fused attention: x2 = softmax(QK^T/8)V + x
        flash<<<dim3(SEQ/128, NZ), 256, SMFL>>>(pqkv, px, px2);

        // --- MLP block ---
        ln_kernel<<<MROWS/8, 256>>>(px2, ln_w, ln_b, pln);

        { PH p = mkph(pln, pw1T, phid, b1, nullptr, DIMM, DIMM, MLPD, 0, DIMM/64);
          gemmh<128,35><<<dim3(MLPD/128, MROWS/128, 1), 256, SMG128>>>(p); }   // bias+gelu+half

        // MLP2: skinny-N -> BN=64 tiles (768 tiles, eff 0.86 vs 0.65)
        { PH p = mkph(phid, pw2T, px, b2, px2, MLPD, MLPD, DIMM, DIMM, MLPD/64);
          gemmh<64,5><<<dim3(DIMM/64, MROWS/128, 1), 256, SMG64>>>(p); }       // bias+resid fp32
    }

    cudaMemcpyAsync(d_out, px, (size_t)MROWS*DIMM*sizeof(float), cudaMemcpyDeviceToDevice);
}

// round 14
// speedup vs baseline: 1.0886x; 1.0886x over previous
#include <cuda_runtime.h>
#include <cuda_fp16.h>
#include <math.h>
#include <stdint.h>

// Problem constants
#define DIMM   768
#define NHEADS 12
#define HDIM   64
#define MLPD   3072
#define NDEPTH 12
#define BATCH  16
#define SEQ    512
#define MROWS  (BATCH*SEQ)    // 8192
#define NZ     (BATCH*NHEADS) // 192
#define QKVN   (3*DIMM)       // 2304

// ---------------- scratch (static device, no allocation) ----------------
__device__ float  g_x  [(size_t)MROWS*DIMM];
__device__ float  g_x2 [(size_t)MROWS*DIMM];
__device__ float  g_bqkv[QKVN];
__device__ __half h_ln [(size_t)MROWS*DIMM];
__device__ __half h_qkv[(size_t)MROWS*QKVN];
__device__ __half h_hid[(size_t)MROWS*MLPD];
__device__ __half h_wqkvT[(size_t)QKVN*DIMM];      // [2304,768] fp16, [N,K]
__device__ __half h_w1T [(size_t)MLPD*DIMM];
__device__ __half h_w2T [(size_t)DIMM*MLPD];

// ---------------- helpers ----------------
__device__ __forceinline__ float gelu_exact(float v){
    return 0.5f * v * (1.0f + erff(v * 0.70710678118654752440f));
}
__device__ __forceinline__ uint32_t smem_u32(const void* p){
    uint32_t a;
    asm("{ .reg .u64 t; cvta.to.shared.u64 t, %1; cvt.u32.u64 %0, t; }" : "=r"(a) : "l"(p));
    return a;
}
__device__ __forceinline__ void cpa16(uint32_t s, const void* g){
    asm volatile("cp.async.cg.shared.global [%0], [%1], 16;" :: "r"(s), "l"(g));
}
__device__ __forceinline__ void cpa_commit(){ asm volatile("cp.async.commit_group;" ::: "memory"); }
template<int N> __device__ __forceinline__ void cpa_wait(){
    asm volatile("cp.async.wait_group %0;" :: "n"(N) : "memory");
}
__device__ __forceinline__ void ldsm4(uint32_t* r, uint32_t addr){
    asm volatile("ldmatrix.sync.aligned.m8n8.x4.shared.b16 {%0,%1,%2,%3}, [%4];"
        : "=r"(r[0]), "=r"(r[1]), "=r"(r[2]), "=r"(r[3]) : "r"(addr));
}
__device__ __forceinline__ void ldsm4t(uint32_t* r, uint32_t addr){
    asm volatile("ldmatrix.sync.aligned.m8n8.x4.trans.shared.b16 {%0,%1,%2,%3}, [%4];"
        : "=r"(r[0]), "=r"(r[1]), "=r"(r[2]), "=r"(r[3]) : "r"(addr));
}
__device__ __forceinline__ void mma_f16(float* d, const uint32_t* a, const uint32_t* b){
    asm volatile(
        "mma.sync.aligned.m16n8k16.row.col.f32.f16.f16.f32 "
        "{%0,%1,%2,%3}, {%4,%5,%6,%7}, {%8,%9}, {%0,%1,%2,%3};\n"
        : "+f"(d[0]), "+f"(d[1]), "+f"(d[2]), "+f"(d[3])
        : "r"(a[0]), "r"(a[1]), "r"(a[2]), "r"(a[3]), "r"(b[0]), "r"(b[1]));
}
__device__ __forceinline__ uint32_t packh2(float x, float y){
    __half2 h = __floats2half2_rn(x, y);
    return *(uint32_t*)&h;
}

// =========================================================================
// fp16 GEMM, fp32 accumulate — round-12 winner (BK=64, BN=128, S=3, 2 CTA/SM)
// EPI bits: 1=+bias, 2=gelu, 4=+residual(fp32), 32=half out (else fp32)
// =========================================================================
struct PH {
    const __half* A; const __half* B; void* C;
    const float* bias; const float* R;
    int lda, ldb, ldc, ldr;
    int nk;         // K / 64
};

template<int EPI>
__global__ __launch_bounds__(256, 2) void gemmh(PH p){
    constexpr int S = 3;
    constexpr int ABYTES = 128*128;           // 16384
    constexpr int STAGE  = 2*ABYTES;          // 32768
    constexpr int NT = 4, MT = 4;

    extern __shared__ char sm[];
    const uint32_t smb = smem_u32(sm);
    const int tid  = threadIdx.x;
    const int lane = tid & 31;
    const int warp = tid >> 5;
    const int wm   = warp >> 2;
    const int wn   = warp & 3;

    const __half* Ag = p.A + (long)blockIdx.y * 128 * p.lda;
    const __half* Bg = p.B + (long)blockIdx.x * 128 * p.ldb;

    float acc[MT][NT][4];
    #pragma unroll
    for(int i=0;i<MT;i++)
        #pragma unroll
        for(int j=0;j<NT;j++){
            acc[i][j][0]=0.f; acc[i][j][1]=0.f; acc[i][j][2]=0.f; acc[i][j][3]=0.f;
        }

    auto load_stage = [&](int kt, int s){
        const uint32_t ab = smb + s*STAGE;
        #pragma unroll
        for(int t=0;t<4;t++){
            int i = tid + t*256, row = i>>3;
            uint32_t u = (uint32_t)(i&7);
            cpa16(ab + (uint32_t)row*128 + (u ^ ((uint32_t)row&7))*16,
                  Ag + (long)row*p.lda + kt*64 + u*8);
        }
        const uint32_t bb = ab + ABYTES;
        #pragma unroll
        for(int t=0;t<4;t++){
            int i = tid + t*256, row = i>>3;
            uint32_t u = (uint32_t)(i&7);
            cpa16(bb + (uint32_t)row*128 + (u ^ ((uint32_t)row&7))*16,
                  Bg + (long)row*p.ldb + kt*64 + u*8);
        }
    };

    const int nk = p.nk;
    #pragma unroll
    for(int s=0;s<S-1;s++){
        if(s < nk) load_stage(s, s);
        cpa_commit();
    }

    int stg = 0;
    for(int kt = 0; kt < nk; kt++){
        cpa_wait<S-2>();
        __syncthreads();
        const uint32_t ab = smb + stg*STAGE;
        const uint32_t bb = ab + ABYTES;

        #pragma unroll
        for(int ks=0; ks<4; ks++){
            uint32_t af[MT][4], bf[NT][2];
            #pragma unroll
            for(int mt=0; mt<MT; mt++){
                uint32_t row = (uint32_t)(wm*64 + mt*16 + ((lane>>3)&1)*8 + (lane&7));
                uint32_t u   = (uint32_t)(ks*2 + (lane>>4));
                ldsm4(af[mt], ab + row*128 + (u ^ (row&7))*16);
            }
            #pragma unroll
            for(int j=0; j<NT/2; j++){
                uint32_t n = (uint32_t)(wn*32 + j*16 + ((lane>>4)&1)*8 + (lane&7));
                uint32_t u = (uint32_t)(ks*2 + ((lane>>3)&1));
                uint32_t r4[4];
                ldsm4(r4, bb + n*128 + (u ^ (n&7))*16);
                bf[2*j][0]=r4[0]; bf[2*j][1]=r4[1]; bf[2*j+1][0]=r4[2]; bf[2*j+1][1]=r4[3];
            }
            #pragma unroll
            for(int mt=0; mt<MT; mt++)
                #pragma unroll
                for(int nt=0; nt<NT; nt++)
                    mma_f16(acc[mt][nt], af[mt], bf[nt]);
        }

        const int nx = kt + S - 1;
        if(nx < nk){
            int ns = stg + (S-1); if(ns >= S) ns -= S;
            load_stage(nx, ns);
        }
        cpa_commit();
        if(++stg == S) stg = 0;
    }

    // ---------------- epilogue ----------------
    const long crow0 = (long)blockIdx.y*128*p.ldc + (long)blockIdx.x*128;
    const float* Rg = nullptr;
    if(EPI & 4)
        Rg = p.R + (long)blockIdx.y*128*p.ldr + (long)blockIdx.x*128;

    #pragma unroll
    for(int mt=0; mt<MT; mt++){
        #pragma unroll
        for(int nt=0; nt<NT; nt++){
            const int col = wn*32 + nt*8 + 2*(lane&3);
            #pragma unroll
            for(int hh=0; hh<2; hh++){
                const int row = wm*64 + mt*16 + (lane>>2) + hh*8;
                float v0 = acc[mt][nt][hh*2], v1 = acc[mt][nt][hh*2+1];
                if(EPI & 1){
                    float2 bb = *(const float2*)&p.bias[blockIdx.x*128 + col];
                    v0 += bb.x; v1 += bb.y;
                }
                if(EPI & 2){ v0 = gelu_exact(v0); v1 = gelu_exact(v1); }
                if(EPI & 4){
                    float2 rv = *(const float2*)(Rg + (long)row*p.ldr + col);
                    v0 += rv.x; v1 += rv.y;
                }
                if(EPI & 32){
                    __half2* Ch = (__half2*)((__half*)p.C + crow0 + (long)row*p.ldc + col);
                    *Ch = __floats2half2_rn(v0, v1);
                }else{
                    float* Cf = (float*)p.C + crow0 + (long)row*p.ldc + col;
                    *(float2*)Cf = make_float2(v0, v1);
                }
            }
        }
    }
}

// =========================================================================
// Fused flash attention, 64-key blocks for 2 CTAs/SM:
//   out = softmax(Q K^T / 8) V + xres
// Grid: (SEQ/128, NZ). 256 threads = 8 warps; warp w owns query rows
// [w*16, w*16+16). Keys streamed in 8 blocks of 64 (2-stage cp.async).
// Smem: Q 16KB + 2 stages x (K 8KB + V 8KB) = 48KB. ~110 regs.
// =========================================================================
__global__ __launch_bounds__(256, 2) void flash(
    const __half* __restrict__ qkv, const float* __restrict__ xres,
    float* __restrict__ out)
{
    extern __shared__ char sm[];
    const uint32_t smb = smem_u32(sm);
    const uint32_t qs  = smb;                       // 16KB Q
    const int tid = threadIdx.x, lane = tid & 31, warp = tid >> 5;
    const int z = blockIdx.y, zb = z / NHEADS, zh = z % NHEADS;
    const long grow0 = (long)zb*SEQ + (long)blockIdx.x*128;

    const __half* Qg = qkv + grow0*QKVN + zh*HDIM;
    const __half* Kg = qkv + (long)zb*SEQ*QKVN + DIMM   + zh*HDIM;
    const __half* Vg = qkv + (long)zb*SEQ*QKVN + 2*DIMM + zh*HDIM;

    // 128-row tile (Q)
    auto ldq = [&](uint32_t dst, const __half* src){
        #pragma unroll
        for(int t=0;t<4;t++){
            int i = tid + t*256, row = i>>3;
            uint32_t u = (uint32_t)(i&7);
            cpa16(dst + (uint32_t)row*128 + (u ^ ((uint32_t)row&7))*16,
                  src + (long)row*QKVN + u*8);
        }
    };
    // 64-row tile (K or V block)
    auto ld64 = [&](uint32_t dst, const __half* src){
        #pragma unroll
        for(int t=0;t<2;t++){
            int i = tid + t*256, row = i>>3;
            uint32_t u = (uint32_t)(i&7);
            cpa16(dst + (uint32_t)row*128 + (u ^ ((uint32_t)row&7))*16,
                  src + (long)row*QKVN + u*8);
        }
    };

    // stages: stage s at smb+16384 + s*16384 (K 8KB + V 8KB)
    ldq(qs, Qg);                                             cpa_commit();
    ld64(smb+16384, Kg);            ld64(smb+24576, Vg);            cpa_commit();
    ld64(smb+32768, Kg + 64l*QKVN); ld64(smb+40960, Vg + 64l*QKVN); cpa_commit();

    cpa_wait<2>();
    __syncthreads();

    uint32_t qf[4][4];
    #pragma unroll
    for(int ks=0; ks<4; ks++){
        uint32_t row = (uint32_t)(warp*16 + ((lane>>3)&1)*8 + (lane&7));
        uint32_t u   = (uint32_t)(2*ks + (lane>>4));
        ldsm4(qf[ks], qs + row*128 + (u ^ (row&7))*16);
    }

    float m0 = -1e30f, m1 = -1e30f, l0 = 0.f, l1 = 0.f;
    float o[8][4];
    #pragma unroll
    for(int nt=0;nt<8;nt++){ o[nt][0]=0.f; o[nt][1]=0.f; o[nt][2]=0.f; o[nt][3]=0.f; }

    for(int kb=0; kb<8; kb++){
        if(kb < 6) cpa_wait<1>(); else cpa_wait<0>();
        __syncthreads();
        const uint32_t kbuf = smb + 16384 + (uint32_t)(kb&1)*16384;
        const uint32_t vbuf = kbuf + 8192;

        // ---- S = Q K^T (64 keys) ----
        float s[8][4];
        #pragma unroll
        for(int nt=0;nt<8;nt++){ s[nt][0]=0.f; s[nt][1]=0.f; s[nt][2]=0.f; s[nt][3]=0.f; }
        #pragma unroll
        for(int ks=0; ks<4; ks++){
            #pragma unroll
            for(int j=0;j<4;j++){
                uint32_t n = (uint32_t)(j*16 + ((lane>>4)&1)*8 + (lane&7));
                uint32_t u = (uint32_t)(2*ks + ((lane>>3)&1));
                uint32_t r4[4];
                ldsm4(r4, kbuf + n*128 + (u ^ (n&7))*16);
                mma_f16(s[2*j  ], qf[ks], r4    );
                mma_f16(s[2*j+1], qf[ks], r4 + 2);
            }
        }

        // ---- online softmax ----
        float cm0 = -1e30f, cm1 = -1e30f;
        #pragma unroll
        for(int nt=0;nt<8;nt++){
            s[nt][0]*=0.125f; s[nt][1]*=0.125f; s[nt][2]*=0.125f; s[nt][3]*=0.125f;
            cm0 = fmaxf(cm0, fmaxf(s[nt][0], s[nt][1]));
            cm1 = fmaxf(cm1, fmaxf(s[nt][2], s[nt][3]));
        }
        cm0 = fmaxf(cm0, __shfl_xor_sync(~0u,cm0,1));
        cm0 = fmaxf(cm0, __shfl_xor_sync(~0u,cm0,2));
        cm1 = fmaxf(cm1, __shfl_xor_sync(~0u,cm1,1));
        cm1 = fmaxf(cm1, __shfl_xor_sync(~0u,cm1,2));
        const float mn0 = fmaxf(m0, cm0), mn1 = fmaxf(m1, cm1);
        const float sf0 = __expf(m0 - mn0), sf1 = __expf(m1 - mn1);
        float sum0 = 0.f, sum1 = 0.f;
        #pragma unroll
        for(int nt=0;nt<8;nt++){
            s[nt][0] = __expf(s[nt][0]-mn0); s[nt][1] = __expf(s[nt][1]-mn0);
            s[nt][2] = __expf(s[nt][2]-mn1); s[nt][3] = __expf(s[nt][3]-mn1);
            sum0 += s[nt][0] + s[nt][1];
            sum1 += s[nt][2] + s[nt][3];
        }
        sum0 += __shfl_xor_sync(~0u,sum0,1); sum0 += __shfl_xor_sync(~0u,sum0,2);
        sum1 += __shfl_xor_sync(~0u,sum1,1); sum1 += __shfl_xor_sync(~0u,sum1,2);
        l0 = l0*sf0 + sum0; l1 = l1*sf1 + sum1;
        m0 = mn0; m1 = mn1;
        #pragma unroll
        for(int nt=0;nt<8;nt++){
            o[nt][0]*=sf0; o[nt][1]*=sf0; o[nt][2]*=sf1; o[nt][3]*=sf1;
        }

        // ---- O += P V  (64 keys = 4 kk steps) ----
        #pragma unroll
        for(int kk=0; kk<4; kk++){
            uint32_t pa[4];
            pa[0] = packh2(s[2*kk  ][0], s[2*kk  ][1]);
            pa[1] = packh2(s[2*kk  ][2], s[2*kk  ][3]);
            pa[2] = packh2(s[2*kk+1][0], s[2*kk+1][1]);
            pa[3] = packh2(s[2*kk+1][2], s[2*kk+1][3]);
            const int g = lane>>3, i = lane&7;
            #pragma unroll
            for(int dp=0; dp<4; dp++){
                uint32_t key = (uint32_t)(kk*16 + (g&1)*8 + i);
                uint32_t dg  = (uint32_t)(dp*2 + (g>>1));
                uint32_t r4[4];
                ldsm4t(r4, vbuf + key*128 + (dg ^ (key&7))*16);
                mma_f16(o[2*dp  ], pa, r4    );
                mma_f16(o[2*dp+1], pa, r4 + 2);
            }
        }

        __syncthreads();
        if(kb + 2 < 8){
            const uint32_t dst = smb + 16384 + (uint32_t)(kb&1)*16384;
            ld64(dst,        Kg + (long)(kb+2)*64*QKVN);
            ld64(dst + 8192, Vg + (long)(kb+2)*64*QKVN);
            cpa_commit();
        }
    }

    // ---- epilogue: O/l + residual, fp32 out ----
    const float inv0 = 1.f/l0, inv1 = 1.f/l1;
    const long gr0 = grow0 + warp*16 + (lane>>2);
    const long gr1 = gr0 + 8;
    const int  col = zh*HDIM + 2*(lane&3);
    #pragma unroll
    for(int nt=0; nt<8; nt++){
        const int c = col + nt*8;
        float2 r0 = *(const float2*)&xres[gr0*DIMM + c];
        float2 r1 = *(const float2*)&xres[gr1*DIMM + c];
        *(float2*)&out[gr0*DIMM + c] = make_float2(o[nt][0]*inv0 + r0.x, o[nt][1]*inv0 + r0.y);
        *(float2*)&out[gr1*DIMM + c] = make_float2(o[nt][2]*inv1 + r1.x, o[nt][3]*inv1 + r1.y);
    }
}

// ---------------- LayerNorm, warp-per-row (round-9, unchanged) -----------------
__global__ __launch_bounds__(256) void ln_kernel(
    const float* __restrict__ x, const float* __restrict__ w,
    const float* __restrict__ b, __half* __restrict__ out)
{
    const int warp = threadIdx.x >> 5, lane = threadIdx.x & 31;
    const long row = (long)blockIdx.x*8 + warp;
    const float4* xr = (const float4*)(x + row*DIMM);

    float4 v[6];
    #pragma unroll
    for(int i=0;i<6;i++) v[i] = xr[lane + i*32];

    float s = 0.f, s2 = 0.f;
    #pragma unroll
    for(int i=0;i<6;i++){
        s  += (v[i].x + v[i].y) + (v[i].z + v[i].w);
        s2 += v[i].x*v[i].x + v[i].y*v[i].y + v[i].z*v[i].z + v[i].w*v[i].w;
    }
    #pragma unroll
    for(int o=16;o;o>>=1){
        s  += __shfl_xor_sync(~0u, s,  o);
        s2 += __shfl_xor_sync(~0u, s2, o);
    }
    const float mu  = s * (1.f/DIMM);
    const float var = s2 * (1.f/DIMM) - mu*mu;
    const float inv = rsqrtf(var + 1e-5f);

    const float4* wv = (const float4*)w;
    const float4* bv = (const float4*)b;
    uint2* orow = (uint2*)(out + row*DIMM);
    #pragma unroll
    for(int i=0;i<6;i++){
        const int c = lane + i*32;
        float4 ww = wv[c], bb = bv[c];
        uint2 pk;
        pk.x = packh2((v[i].x - mu)*inv*ww.x + bb.x, (v[i].y - mu)*inv*ww.y + bb.y);
        pk.y = packh2((v[i].z - mu)*inv*ww.z + bb.z, (v[i].w - mu)*inv*ww.w + bb.w);
        orow[c] = pk;
    }
}

// ---------------- weight transpose [K,N] fp32 -> [N,K] fp16 --------------------
__global__ void wtrans(const float* __restrict__ in, __half* __restrict__ out, int K, int N){
    __shared__ float t[32][33];
    const int k0 = blockIdx.y*32, n0 = blockIdx.x*32;
    const int tx = threadIdx.x & 31, ty = threadIdx.x >> 5;
    #pragma unroll
    for(int i=0;i<4;i++)
        t[ty+8*i][tx] = in[(size_t)(k0+ty+8*i)*N + n0+tx];
    __syncthreads();
    #pragma unroll
    for(int i=0;i<4;i++)
        out[(size_t)(n0+ty+8*i)*K + k0+tx] = __float2half_rn(t[tx][ty+8*i]);
}

__global__ void concat_bias(const float* a, const float* b, const float* c, float* o){
    int i = blockIdx.x*256 + threadIdx.x;
    if(i < DIMM){ o[i] = a[i]; o[i+DIMM] = b[i]; o[i+2*DIMM] = c[i]; }
}

// ---------------- host ----------------
static PH mkph(const __half* A, const __half* B, void* C, const float* bias,
               const float* R, int lda, int ldb, int ldc, int ldr, int nk){
    PH p{};
    p.A=A; p.B=B; p.C=C; p.bias=bias; p.R=R;
    p.lda=lda; p.ldb=ldb; p.ldc=ldc; p.ldr=ldr;
    p.nk=nk;
    return p;
}

extern "C" void kernel_launch(void* const* d_in, const int* in_sizes, int n_in,
                              void* d_out, int out_size){
    const float* x    = (const float*)d_in[0];
    const float* ln_w = (const float*)d_in[1];
    const float* ln_b = (const float*)d_in[2];
    const float* wq   = (const float*)d_in[3];
    const float* bq   = (const float*)d_in[4];
    const float* wk   = (const float*)d_in[5];
    const float* bk   = (const float*)d_in[6];
    const float* wv   = (const float*)d_in[7];
    const float* bv   = (const float*)d_in[8];
    const float* w1   = (const float*)d_in[9];
    const float* b1   = (const float*)d_in[10];
    const float* w2   = (const float*)d_in[11];
    const float* b2   = (const float*)d_in[12];

    float *px, *px2, *pbqkv;
    __half *pln, *pqkv, *phid, *pwqkvT, *pw1T, *pw2T;
    cudaGetSymbolAddress((void**)&px    , g_x   );
    cudaGetSymbolAddress((void**)&px2   , g_x2  );
    cudaGetSymbolAddress((void**)&pbqkv , g_bqkv);
    cudaGetSymbolAddress((void**)&pln   , h_ln  );
    cudaGetSymbolAddress((void**)&pqkv  , h_qkv );
    cudaGetSymbolAddress((void**)&phid  , h_hid );
    cudaGetSymbolAddress((void**)&pwqkvT, h_wqkvT);
    cudaGetSymbolAddress((void**)&pw1T  , h_w1T );
    cudaGetSymbolAddress((void**)&pw2T  , h_w2T );

    const int SMG  = 3*32768;                // 98304 (2 CTAs/SM = 192KB)
    const int SMFL = 16384 + 2*16384;        // 49152 (2 CTAs/SM = 96KB)
    cudaFuncSetAttribute(gemmh<33>, cudaFuncAttributeMaxDynamicSharedMemorySize, SMG);
    cudaFuncSetAttribute(gemmh<35>, cudaFuncAttributeMaxDynamicSharedMemorySize, SMG);
    cudaFuncSetAttribute(gemmh< 5>, cudaFuncAttributeMaxDynamicSharedMemorySize, SMG);
    cudaFuncSetAttribute(flash,     cudaFuncAttributeMaxDynamicSharedMemorySize, SMFL);

    // weight prep (amortized over 12 layers)
    wtrans<<<dim3(DIMM/32, DIMM/32), 256>>>(wq, pwqkvT,                       DIMM, DIMM);
    wtrans<<<dim3(DIMM/32, DIMM/32), 256>>>(wk, pwqkvT + (size_t)DIMM*DIMM,   DIMM, DIMM);
    wtrans<<<dim3(DIMM/32, DIMM/32), 256>>>(wv, pwqkvT + (size_t)2*DIMM*DIMM, DIMM, DIMM);
    wtrans<<<dim3(MLPD/32, DIMM/32), 256>>>(w1, pw1T, DIMM, MLPD);
    wtrans<<<dim3(DIMM/32, MLPD/32), 256>>>(w2, pw2T, MLPD, DIMM);
    concat_bias<<<3, 256>>>(bq, bk, bv, pbqkv);

    // residual stream: layer 0 reads the harness input directly (no copy);
    // layer 11's MLP2 writes d_out directly (no final copy).
    const float* cur = x;

    for(int l=0; l<NDEPTH; l++){
        // --- attention block ---
        ln_kernel<<<MROWS/8, 256>>>(cur, ln_w, ln_b, pln);

        // fused QKV: [8192,2304] ; bias, half out
        { PH p = mkph(pln, pwqkvT, pqkv, pbqkv, nullptr, DIMM, DIMM, QKVN, 0, DIMM/64);
          gemmh<33><<<dim3(QKVN/128, MROWS/128, 1), 256, SMG>>>(p); }

        // fused attention: x2 = softmax(QK^T/8)V + cur
        flash<<<dim3(SEQ/128, NZ), 256, SMFL>>>(pqkv, cur, px2);

        // --- MLP block ---
        ln_kernel<<<MROWS/8, 256>>>(px2, ln_w, ln_b, pln);

        { PH p = mkph(pln, pw1T, phid, b1, nullptr, DIMM, DIMM, MLPD, 0, DIMM/64);
          gemmh<35><<<dim3(MLPD/128, MROWS/128, 1), 256, SMG>>>(p); }   // bias+gelu+half

        float* dst = (l == NDEPTH-1) ? (float*)d_out : px;
        { PH p = mkph(phid, pw2T, dst, b2, px2, MLPD, MLPD, DIMM, DIMM, MLPD/64);
          gemmh<5><<<dim3(DIMM/128, MROWS/128, 1), 256, SMG>>>(p); }    // bias+resid fp32
        cur = dst;
    }
}

// round 16
// speedup vs baseline: 1.1377x; 1.0451x over previous
#include <cuda_runtime.h>
#include <cuda_fp16.h>
#include <math.h>
#include <stdint.h>

// Problem constants
#define DIMM   768
#define NHEADS 12
#define HDIM   64
#define MLPD   3072
#define NDEPTH 12
#define BATCH  16
#define SEQ    512
#define MROWS  (BATCH*SEQ)    // 8192
#define NZ     (BATCH*NHEADS) // 192
#define QKVN   (3*DIMM)       // 2304

// ---------------- scratch (static device, no allocation) ----------------
__device__ float  g_x  [(size_t)MROWS*DIMM];
__device__ float  g_x2 [(size_t)MROWS*DIMM];
__device__ float  g_bqkv[QKVN];
__device__ __half h_ln [(size_t)MROWS*DIMM];
__device__ __half h_qkv[(size_t)MROWS*QKVN];
__device__ __half h_hid[(size_t)MROWS*MLPD];
__device__ __half h_wqkvT[(size_t)QKVN*DIMM];      // [2304,768] fp16, [N,K]
__device__ __half h_w1T [(size_t)MLPD*DIMM];
__device__ __half h_w2T [(size_t)DIMM*MLPD];

// ---------------- helpers ----------------
__device__ __forceinline__ float gelu_exact(float v){
    return 0.5f * v * (1.0f + erff(v * 0.70710678118654752440f));
}
__device__ __forceinline__ uint32_t smem_u32(const void* p){
    uint32_t a;
    asm("{ .reg .u64 t; cvta.to.shared.u64 t, %1; cvt.u32.u64 %0, t; }" : "=r"(a) : "l"(p));
    return a;
}
__device__ __forceinline__ void cpa16(uint32_t s, const void* g){
    asm volatile("cp.async.cg.shared.global [%0], [%1], 16;" :: "r"(s), "l"(g));
}
__device__ __forceinline__ void cpa_commit(){ asm volatile("cp.async.commit_group;" ::: "memory"); }
template<int N> __device__ __forceinline__ void cpa_wait(){
    asm volatile("cp.async.wait_group %0;" :: "n"(N) : "memory");
}
__device__ __forceinline__ void ldsm4(uint32_t* r, uint32_t addr){
    asm volatile("ldmatrix.sync.aligned.m8n8.x4.shared.b16 {%0,%1,%2,%3}, [%4];"
        : "=r"(r[0]), "=r"(r[1]), "=r"(r[2]), "=r"(r[3]) : "r"(addr));
}
__device__ __forceinline__ void ldsm4t(uint32_t* r, uint32_t addr){
    asm volatile("ldmatrix.sync.aligned.m8n8.x4.trans.shared.b16 {%0,%1,%2,%3}, [%4];"
        : "=r"(r[0]), "=r"(r[1]), "=r"(r[2]), "=r"(r[3]) : "r"(addr));
}
__device__ __forceinline__ void mma_f16(float* d, const uint32_t* a, const uint32_t* b){
    asm volatile(
        "mma.sync.aligned.m16n8k16.row.col.f32.f16.f16.f32 "
        "{%0,%1,%2,%3}, {%4,%5,%6,%7}, {%8,%9}, {%0,%1,%2,%3};\n"
        : "+f"(d[0]), "+f"(d[1]), "+f"(d[2]), "+f"(d[3])
        : "r"(a[0]), "r"(a[1]), "r"(a[2]), "r"(a[3]), "r"(b[0]), "r"(b[1]));
}
__device__ __forceinline__ uint32_t packh2(float x, float y){
    __half2 h = __floats2half2_rn(x, y);
    return *(uint32_t*)&h;
}

// =========================================================================
// fp16 GEMM, fp32 accumulate — round-12 pipeline (BK=64, BN=128, S=3,
// 2 CTAs/SM) with COMPILE-TIME k-trip count NKT:
//   NKT>0  -> k-loop fully unrolled, stage indices constant, no bookkeeping
//   NKT==0 -> runtime trip count (used for MLP2, nk=48, to keep I$ small)
// EPI bits: 1=+bias, 2=gelu, 4=+residual(fp32), 32=half out (else fp32)
// =========================================================================
struct PH {
    const __half* A; const __half* B; void* C;
    const float* bias; const float* R;
    int lda, ldb, ldc, ldr;
    int nk;         // K / 64 (used when NKT==0)
};

template<int EPI, int NKT>
__global__ __launch_bounds__(256, 2) void gemmh(PH p){
    constexpr int S = 3;
    constexpr int ABYTES = 128*128;           // 16384
    constexpr int STAGE  = 2*ABYTES;          // 32768
    constexpr int NT = 4, MT = 4;

    extern __shared__ char sm[];
    const uint32_t smb = smem_u32(sm);
    const int tid  = threadIdx.x;
    const int lane = tid & 31;
    const int warp = tid >> 5;
    const int wm   = warp >> 2;
    const int wn   = warp & 3;

    const __half* Ag = p.A + (long)blockIdx.y * 128 * p.lda;
    const __half* Bg = p.B + (long)blockIdx.x * 128 * p.ldb;

    float acc[MT][NT][4];
    #pragma unroll
    for(int i=0;i<MT;i++)
        #pragma unroll
        for(int j=0;j<NT;j++){
            acc[i][j][0]=0.f; acc[i][j][1]=0.f; acc[i][j][2]=0.f; acc[i][j][3]=0.f;
        }

    auto load_stage = [&](int kt, int s){
        const uint32_t ab = smb + s*STAGE;
        #pragma unroll
        for(int t=0;t<4;t++){
            int i = tid + t*256, row = i>>3;
            uint32_t u = (uint32_t)(i&7);
            cpa16(ab + (uint32_t)row*128 + (u ^ ((uint32_t)row&7))*16,
                  Ag + (long)row*p.lda + kt*64 + u*8);
        }
        const uint32_t bb = ab + ABYTES;
        #pragma unroll
        for(int t=0;t<4;t++){
            int i = tid + t*256, row = i>>3;
            uint32_t u = (uint32_t)(i&7);
            cpa16(bb + (uint32_t)row*128 + (u ^ ((uint32_t)row&7))*16,
                  Bg + (long)row*p.ldb + kt*64 + u*8);
        }
    };

    auto body = [&](int kt, int stg, int nk){
        cpa_wait<S-2>();
        __syncthreads();
        const uint32_t ab = smb + stg*STAGE;
        const uint32_t bb = ab + ABYTES;

        #pragma unroll
        for(int ks=0; ks<4; ks++){
            uint32_t af[MT][4], bf[NT][2];
            #pragma unroll
            for(int mt=0; mt<MT; mt++){
                uint32_t row = (uint32_t)(wm*64 + mt*16 + ((lane>>3)&1)*8 + (lane&7));
                uint32_t u   = (uint32_t)(ks*2 + (lane>>4));
                ldsm4(af[mt], ab + row*128 + (u ^ (row&7))*16);
            }
            #pragma unroll
            for(int j=0; j<NT/2; j++){
                uint32_t n = (uint32_t)(wn*32 + j*16 + ((lane>>4)&1)*8 + (lane&7));
                uint32_t u = (uint32_t)(ks*2 + ((lane>>3)&1));
                uint32_t r4[4];
                ldsm4(r4, bb + n*128 + (u ^ (n&7))*16);
                bf[2*j][0]=r4[0]; bf[2*j][1]=r4[1]; bf[2*j+1][0]=r4[2]; bf[2*j+1][1]=r4[3];
            }
            #pragma unroll
            for(int mt=0; mt<MT; mt++)
                #pragma unroll
                for(int nt=0; nt<NT; nt++)
                    mma_f16(acc[mt][nt], af[mt], bf[nt]);
        }

        const int nx = kt + S - 1;
        if(nx < nk) load_stage(nx, nx % S);
        cpa_commit();
    };

    if constexpr (NKT > 0){
        #pragma unroll
        for(int s=0;s<S-1;s++){
            if(s < NKT) load_stage(s, s);
            cpa_commit();
        }
        #pragma unroll
        for(int kt = 0; kt < NKT; kt++)
            body(kt, kt % S, NKT);
    } else {
        const int nk = p.nk;
        #pragma unroll
        for(int s=0;s<S-1;s++){
            if(s < nk) load_stage(s, s);
            cpa_commit();
        }
        int stg = 0;
        for(int kt = 0; kt < nk; kt++){
            body(kt, stg, nk);
            if(++stg == S) stg = 0;
        }
    }

    // ---------------- epilogue ----------------
    const long crow0 = (long)blockIdx.y*128*p.ldc + (long)blockIdx.x*128;
    const float* Rg = nullptr;
    if(EPI & 4)
        Rg = p.R + (long)blockIdx.y*128*p.ldr + (long)blockIdx.x*128;

    #pragma unroll
    for(int mt=0; mt<MT; mt++){
        #pragma unroll
        for(int nt=0; nt<NT; nt++){
            const int col = wn*32 + nt*8 + 2*(lane&3);
            #pragma unroll
            for(int hh=0; hh<2; hh++){
                const int row = wm*64 + mt*16 + (lane>>2) + hh*8;
                float v0 = acc[mt][nt][hh*2], v1 = acc[mt][nt][hh*2+1];
                if(EPI & 1){
                    float2 bb = *(const float2*)&p.bias[blockIdx.x*128 + col];
                    v0 += bb.x; v1 += bb.y;
                }
                if(EPI & 2){ v0 = gelu_exact(v0); v1 = gelu_exact(v1); }
                if(EPI & 4){
                    float2 rv = *(const float2*)(Rg + (long)row*p.ldr + col);
                    v0 += rv.x; v1 += rv.y;
                }
                if(EPI & 32){
                    __half2* Ch = (__half2*)((__half*)p.C + crow0 + (long)row*p.ldc + col);
                    *Ch = __floats2half2_rn(v0, v1);
                }else{
                    float* Cf = (float*)p.C + crow0 + (long)row*p.ldc + col;
                    *(float2*)Cf = make_float2(v0, v1);
                }
            }
        }
    }
}

// =========================================================================
// Fused flash attention, 64-key blocks, 2 CTAs/SM (round-14, unchanged)
// =========================================================================
__global__ __launch_bounds__(256, 2) void flash(
    const __half* __restrict__ qkv, const float* __restrict__ xres,
    float* __restrict__ out)
{
    extern __shared__ char sm[];
    const uint32_t smb = smem_u32(sm);
    const uint32_t qs  = smb;
    const int tid = threadIdx.x, lane = tid & 31, warp = tid >> 5;
    const int z = blockIdx.y, zb = z / NHEADS, zh = z % NHEADS;
    const long grow0 = (long)zb*SEQ + (long)blockIdx.x*128;

    const __half* Qg = qkv + grow0*QKVN + zh*HDIM;
    const __half* Kg = qkv + (long)zb*SEQ*QKVN + DIMM   + zh*HDIM;
    const __half* Vg = qkv + (long)zb*SEQ*QKVN + 2*DIMM + zh*HDIM;

    auto ldq = [&](uint32_t dst, const __half* src){
        #pragma unroll
        for(int t=0;t<4;t++){
            int i = tid + t*256, row = i>>3;
            uint32_t u = (uint32_t)(i&7);
            cpa16(dst + (uint32_t)row*128 + (u ^ ((uint32_t)row&7))*16,
                  src + (long)row*QKVN + u*8);
        }
    };
    auto ld64 = [&](uint32_t dst, const __half* src){
        #pragma unroll
        for(int t=0;t<2;t++){
            int i = tid + t*256, row = i>>3;
            uint32_t u = (uint32_t)(i&7);
            cpa16(dst + (uint32_t)row*128 + (u ^ ((uint32_t)row&7))*16,
                  src + (long)row*QKVN + u*8);
        }
    };

    ldq(qs, Qg);                                             cpa_commit();
    ld64(smb+16384, Kg);            ld64(smb+24576, Vg);            cpa_commit();
    ld64(smb+32768, Kg + 64l*QKVN); ld64(smb+40960, Vg + 64l*QKVN); cpa_commit();

    cpa_wait<2>();
    __syncthreads();

    uint32_t qf[4][4];
    #pragma unroll
    for(int ks=0; ks<4; ks++){
        uint32_t row = (uint32_t)(warp*16 + ((lane>>3)&1)*8 + (lane&7));
        uint32_t u   = (uint32_t)(2*ks + (lane>>4));
        ldsm4(qf[ks], qs + row*128 + (u ^ (row&7))*16);
    }

    float m0 = -1e30f, m1 = -1e30f, l0 = 0.f, l1 = 0.f;
    float o[8][4];
    #pragma unroll
    for(int nt=0;nt<8;nt++){ o[nt][0]=0.f; o[nt][1]=0.f; o[nt][2]=0.f; o[nt][3]=0.f; }

    for(int kb=0; kb<8; kb++){
        if(kb < 6) cpa_wait<1>(); else cpa_wait<0>();
        __syncthreads();
        const uint32_t kbuf = smb + 16384 + (uint32_t)(kb&1)*16384;
        const uint32_t vbuf = kbuf + 8192;

        float s[8][4];
        #pragma unroll
        for(int nt=0;nt<8;nt++){ s[nt][0]=0.f; s[nt][1]=0.f; s[nt][2]=0.f; s[nt][3]=0.f; }
        #pragma unroll
        for(int ks=0; ks<4; ks++){
            #pragma unroll
            for(int j=0;j<4;j++){
                uint32_t n = (uint32_t)(j*16 + ((lane>>4)&1)*8 + (lane&7));
                uint32_t u = (uint32_t)(2*ks + ((lane>>3)&1));
                uint32_t r4[4];
                ldsm4(r4, kbuf + n*128 + (u ^ (n&7))*16);
                mma_f16(s[2*j  ], qf[ks], r4    );
                mma_f16(s[2*j+1], qf[ks], r4 + 2);
            }
        }

        float cm0 = -1e30f, cm1 = -1e30f;
        #pragma unroll
        for(int nt=0;nt<8;nt++){
            s[nt][0]*=0.125f; s[nt][1]*=0.125f; s[nt][2]*=0.125f; s[nt][3]*=0.125f;
            cm0 = fmaxf(cm0, fmaxf(s[nt][0], s[nt][1]));
            cm1 = fmaxf(cm1, fmaxf(s[nt][2], s[nt][3]));
        }
        cm0 = fmaxf(cm0, __shfl_xor_sync(~0u,cm0,1));
        cm0 = fmaxf(cm0, __shfl_xor_sync(~0u,cm0,2));
        cm1 = fmaxf(cm1, __shfl_xor_sync(~0u,cm1,1));
        cm1 = fmaxf(cm1, __shfl_xor_sync(~0u,cm1,2));
        const float mn0 = fmaxf(m0, cm0), mn1 = fmaxf(m1, cm1);
        const float sf0 = __expf(m0 - mn0), sf1 = __expf(m1 - mn1);
        float sum0 = 0.f, sum1 = 0.f;
        #pragma unroll
        for(int nt=0;nt<8;nt++){
            s[nt][0] = __expf(s[nt][0]-mn0); s[nt][1] = __expf(s[nt][1]-mn0);
            s[nt][2] = __expf(s[nt][2]-mn1); s[nt][3] = __expf(s[nt][3]-mn1);
            sum0 += s[nt][0] + s[nt][1];
            sum1 += s[nt][2] + s[nt][3];
        }
        sum0 += __shfl_xor_sync(~0u,sum0,1); sum0 += __shfl_xor_sync(~0u,sum0,2);
        sum1 += __shfl_xor_sync(~0u,sum1,1); sum1 += __shfl_xor_sync(~0u,sum1,2);
        l0 = l0*sf0 + sum0; l1 = l1*sf1 + sum1;
        m0 = mn0; m1 = mn1;
        #pragma unroll
        for(int nt=0;nt<8;nt++){
            o[nt][0]*=sf0; o[nt][1]*=sf0; o[nt][2]*=sf1; o[nt][3]*=sf1;
        }

        #pragma unroll
        for(int kk=0; kk<4; kk++){
            uint32_t pa[4];
            pa[0] = packh2(s[2*kk  ][0], s[2*kk  ][1]);
            pa[1] = packh2(s[2*kk  ][2], s[2*kk  ][3]);
            pa[2] = packh2(s[2*kk+1][0], s[2*kk+1][1]);
            pa[3] = packh2(s[2*kk+1][2], s[2*kk+1][3]);
            const int g = lane>>3, i = lane&7;
            #pragma unroll
            for(int dp=0; dp<4; dp++){
                uint32_t key = (uint32_t)(kk*16 + (g&1)*8 + i);
                uint32_t dg  = (uint32_t)(dp*2 + (g>>1));
                uint32_t r4[4];
                ldsm4t(r4, vbuf + key*128 + (dg ^ (key&7))*16);
                mma_f16(o[2*dp  ], pa, r4    );
                mma_f16(o[2*dp+1], pa, r4 + 2);
            }
        }

        __syncthreads();
        if(kb + 2 < 8){
            const uint32_t dst = smb + 16384 + (uint32_t)(kb&1)*16384;
            ld64(dst,        Kg + (long)(kb+2)*64*QKVN);
            ld64(dst + 8192, Vg + (long)(kb+2)*64*QKVN);
            cpa_commit();
        }
    }

    const float inv0 = 1.f/l0, inv1 = 1.f/l1;
    const long gr0 = grow0 + warp*16 + (lane>>2);
    const long gr1 = gr0 + 8;
    const int  col = zh*HDIM + 2*(lane&3);
    #pragma unroll
    for(int nt=0; nt<8; nt++){
        const int c = col + nt*8;
        float2 r0 = *(const float2*)&xres[gr0*DIMM + c];
        float2 r1 = *(const float2*)&xres[gr1*DIMM + c];
        *(float2*)&out[gr0*DIMM + c] = make_float2(o[nt][0]*inv0 + r0.x, o[nt][1]*inv0 + r0.y);
        *(float2*)&out[gr1*DIMM + c] = make_float2(o[nt][2]*inv1 + r1.x, o[nt][3]*inv1 + r1.y);
    }
}

// ---------------- LayerNorm, warp-per-row (round-9, unchanged) -----------------
__global__ __launch_bounds__(256) void ln_kernel(
    const float* __restrict__ x, const float* __restrict__ w,
    const float* __restrict__ b, __half* __restrict__ out)
{
    const int warp = threadIdx.x >> 5, lane = threadIdx.x & 31;
    const long row = (long)blockIdx.x*8 + warp;
    const float4* xr = (const float4*)(x + row*DIMM);

    float4 v[6];
    #pragma unroll
    for(int i=0;i<6;i++) v[i] = xr[lane + i*32];

    float s = 0.f, s2 = 0.f;
    #pragma unroll
    for(int i=0;i<6;i++){
        s  += (v[i].x + v[i].y) + (v[i].z + v[i].w);
        s2 += v[i].x*v[i].x + v[i].y*v[i].y + v[i].z*v[i].z + v[i].w*v[i].w;
    }
    #pragma unroll
    for(int o=16;o;o>>=1){
        s  += __shfl_xor_sync(~0u, s,  o);
        s2 += __shfl_xor_sync(~0u, s2, o);
    }
    const float mu  = s * (1.f/DIMM);
    const float var = s2 * (1.f/DIMM) - mu*mu;
    const float inv = rsqrtf(var + 1e-5f);

    const float4* wv = (const float4*)w;
    const float4* bv = (const float4*)b;
    uint2* orow = (uint2*)(out + row*DIMM);
    #pragma unroll
    for(int i=0;i<6;i++){
        const int c = lane + i*32;
        float4 ww = wv[c], bb = bv[c];
        uint2 pk;
        pk.x = packh2((v[i].x - mu)*inv*ww.x + bb.x, (v[i].y - mu)*inv*ww.y + bb.y);
        pk.y = packh2((v[i].z - mu)*inv*ww.z + bb.z, (v[i].w - mu)*inv*ww.w + bb.w);
        orow[c] = pk;
    }
}

// ---------------- weight transpose [K,N] fp32 -> [N,K] fp16 --------------------
__global__ void wtrans(const float* __restrict__ in, __half* __restrict__ out, int K, int N){
    __shared__ float t[32][33];
    const int k0 = blockIdx.y*32, n0 = blockIdx.x*32;
    const int tx = threadIdx.x & 31, ty = threadIdx.x >> 5;
    #pragma unroll
    for(int i=0;i<4;i++)
        t[ty+8*i][tx] = in[(size_t)(k0+ty+8*i)*N + n0+tx];
    __syncthreads();
    #pragma unroll
    for(int i=0;i<4;i++)
        out[(size_t)(n0+ty+8*i)*K + k0+tx] = __float2half_rn(t[tx][ty+8*i]);
}

__global__ void concat_bias(const float* a, const float* b, const float* c, float* o){
    int i = blockIdx.x*256 + threadIdx.x;
    if(i < DIMM){ o[i] = a[i]; o[i+DIMM] = b[i]; o[i+2*DIMM] = c[i]; }
}

// ---------------- host ----------------
static PH mkph(const __half* A, const __half* B, void* C, const float* bias,
               const float* R, int lda, int ldb, int ldc, int ldr, int nk){
    PH p{};
    p.A=A; p.B=B; p.C=C; p.bias=bias; p.R=R;
    p.lda=lda; p.ldb=ldb; p.ldc=ldc; p.ldr=ldr;
    p.nk=nk;
    return p;
}

extern "C" void kernel_launch(void* const* d_in, const int* in_sizes, int n_in,
                              void* d_out, int out_size){
    const float* x    = (const float*)d_in[0];
    const float* ln_w = (const float*)d_in[1];
    const float* ln_b = (const float*)d_in[2];
    const float* wq   = (const float*)d_in[3];
    const float* bq   = (const float*)d_in[4];
    const float* wk   = (const float*)d_in[5];
    const float* bk   = (const float*)d_in[6];
    const float* wv   = (const float*)d_in[7];
    const float* bv   = (const float*)d_in[8];
    const float* w1   = (const float*)d_in[9];
    const float* b1   = (const float*)d_in[10];
    const float* w2   = (const float*)d_in[11];
    const float* b2   = (const float*)d_in[12];

    float *px, *px2, *pbqkv;
    __half *pln, *pqkv, *phid, *pwqkvT, *pw1T, *pw2T;
    cudaGetSymbolAddress((void**)&px    , g_x   );
    cudaGetSymbolAddress((void**)&px2   , g_x2  );
    cudaGetSymbolAddress((void**)&pbqkv , g_bqkv);
    cudaGetSymbolAddress((void**)&pln   , h_ln  );
    cudaGetSymbolAddress((void**)&pqkv  , h_qkv );
    cudaGetSymbolAddress((void**)&phid  , h_hid );
    cudaGetSymbolAddress((void**)&pwqkvT, h_wqkvT);
    cudaGetSymbolAddress((void**)&pw1T  , h_w1T );
    cudaGetSymbolAddress((void**)&pw2T  , h_w2T );

    const int SMG  = 3*32768;                // 98304 (2 CTAs/SM = 192KB)
    const int SMFL = 16384 + 2*16384;        // 49152 (2 CTAs/SM = 96KB)
    cudaFuncSetAttribute(gemmh<33,12>, cudaFuncAttributeMaxDynamicSharedMemorySize, SMG);
    cudaFuncSetAttribute(gemmh<35,12>, cudaFuncAttributeMaxDynamicSharedMemorySize, SMG);
    cudaFuncSetAttribute(gemmh< 5, 0>, cudaFuncAttributeMaxDynamicSharedMemorySize, SMG);
    cudaFuncSetAttribute(flash,        cudaFuncAttributeMaxDynamicSharedMemorySize, SMFL);

    // weight prep (amortized over 12 layers)
    wtrans<<<dim3(DIMM/32, DIMM/32), 256>>>(wq, pwqkvT,                       DIMM, DIMM);
    wtrans<<<dim3(DIMM/32, DIMM/32), 256>>>(wk, pwqkvT + (size_t)DIMM*DIMM,   DIMM, DIMM);
    wtrans<<<dim3(DIMM/32, DIMM/32), 256>>>(wv, pwqkvT + (size_t)2*DIMM*DIMM, DIMM, DIMM);
    wtrans<<<dim3(MLPD/32, DIMM/32), 256>>>(w1, pw1T, DIMM, MLPD);
    wtrans<<<dim3(DIMM/32, MLPD/32), 256>>>(w2, pw2T, MLPD, DIMM);
    concat_bias<<<3, 256>>>(bq, bk, bv, pbqkv);

    // residual stream: layer 0 reads the harness input directly (no copy);
    // layer 11's MLP2 writes d_out directly (no final copy).
    const float* cur = x;

    for(int l=0; l<NDEPTH; l++){
        // --- attention block ---
        ln_kernel<<<MROWS/8, 256>>>(cur, ln_w, ln_b, pln);

        // fused QKV: [8192,2304] ; bias, half out  (nk=12 compile-time)
        { PH p = mkph(pln, pwqkvT, pqkv, pbqkv, nullptr, DIMM, DIMM, QKVN, 0, DIMM/64);
          gemmh<33,12><<<dim3(QKVN/128, MROWS/128, 1), 256, SMG>>>(p); }

        // fused attention: x2 = softmax(QK^T/8)V + cur
        flash<<<dim3(SEQ/128, NZ), 256, SMFL>>>(pqkv, cur, px2);

        // --- MLP block ---
        ln_kernel<<<MROWS/8, 256>>>(px2, ln_w, ln_b, pln);

        { PH p = mkph(pln, pw1T, phid, b1, nullptr, DIMM, DIMM, MLPD, 0, DIMM/64);
          gemmh<35,12><<<dim3(MLPD/128, MROWS/128, 1), 256, SMG>>>(p); }  // bias+gelu+half

        float* dst = (l == NDEPTH-1) ? (float*)d_out : px;
        { PH p = mkph(phid, pw2T, dst, b2, px2, MLPD, MLPD, DIMM, DIMM, MLPD/64);
          gemmh<5,0><<<dim3(DIMM/128, MROWS/128, 1), 256, SMG>>>(p); }    // bias+resid fp32
        cur = dst;
    }
}

// round 17
// speedup vs baseline: 1.1443x; 1.0058x over previous
#include <cuda_runtime.h>
#include <cuda_fp16.h>
#include <math.h>
#include <stdint.h>

// Problem constants
#define DIMM   768
#define NHEADS 12
#define HDIM   64
#define MLPD   3072
#define NDEPTH 12
#define BATCH  16
#define SEQ    512
#define MROWS  (BATCH*SEQ)    // 8192
#define NZ     (BATCH*NHEADS) // 192
#define QKVN   (3*DIMM)       // 2304

// ---------------- scratch (static device, no allocation) ----------------
__device__ float  g_x  [(size_t)MROWS*DIMM];
__device__ float  g_x2 [(size_t)MROWS*DIMM];
__device__ float  g_bqkv[QKVN];
__device__ __half h_ln [(size_t)MROWS*DIMM];
__device__ __half h_qkv[(size_t)MROWS*QKVN];
__device__ __half h_hid[(size_t)MROWS*MLPD];
__device__ __half h_wqkvT[(size_t)QKVN*DIMM];      // [2304,768] fp16, [N,K]
__device__ __half h_w1T [(size_t)MLPD*DIMM];
__device__ __half h_w2T [(size_t)DIMM*MLPD];

// ---------------- helpers ----------------
__device__ __forceinline__ float gelu_exact(float v){
    return 0.5f * v * (1.0f + erff(v * 0.70710678118654752440f));
}
__device__ __forceinline__ uint32_t smem_u32(const void* p){
    uint32_t a;
    asm("{ .reg .u64 t; cvta.to.shared.u64 t, %1; cvt.u32.u64 %0, t; }" : "=r"(a) : "l"(p));
    return a;
}
__device__ __forceinline__ void cpa16(uint32_t s, const void* g){
    asm volatile("cp.async.cg.shared.global [%0], [%1], 16;" :: "r"(s), "l"(g));
}
__device__ __forceinline__ void cpa_commit(){ asm volatile("cp.async.commit_group;" ::: "memory"); }
template<int N> __device__ __forceinline__ void cpa_wait(){
    asm volatile("cp.async.wait_group %0;" :: "n"(N) : "memory");
}
__device__ __forceinline__ void ldsm4(uint32_t* r, uint32_t addr){
    asm volatile("ldmatrix.sync.aligned.m8n8.x4.shared.b16 {%0,%1,%2,%3}, [%4];"
        : "=r"(r[0]), "=r"(r[1]), "=r"(r[2]), "=r"(r[3]) : "r"(addr));
}
__device__ __forceinline__ void ldsm4t(uint32_t* r, uint32_t addr){
    asm volatile("ldmatrix.sync.aligned.m8n8.x4.trans.shared.b16 {%0,%1,%2,%3}, [%4];"
        : "=r"(r[0]), "=r"(r[1]), "=r"(r[2]), "=r"(r[3]) : "r"(addr));
}
__device__ __forceinline__ void mma_f16(float* d, const uint32_t* a, const uint32_t* b){
    asm volatile(
        "mma.sync.aligned.m16n8k16.row.col.f32.f16.f16.f32 "
        "{%0,%1,%2,%3}, {%4,%5,%6,%7}, {%8,%9}, {%0,%1,%2,%3};\n"
        : "+f"(d[0]), "+f"(d[1]), "+f"(d[2]), "+f"(d[3])
        : "r"(a[0]), "r"(a[1]), "r"(a[2]), "r"(a[3]), "r"(b[0]), "r"(b[1]));
}
__device__ __forceinline__ uint32_t packh2(float x, float y){
    __half2 h = __floats2half2_rn(x, y);
    return *(uint32_t*)&h;
}

// =========================================================================
// fp16 GEMM, fp32 accumulate — round-12 pipeline (BK=64, BN=128, S=3,
// 2 CTAs/SM) with COMPILE-TIME stage indices everywhere:
//   NKT>0  -> k-loop fully unrolled (QKV/MLP1, nk=12)
//   NKT==0 -> runtime trip count but UNROLLED BY S=3 so stage offsets are
//             immediates and the stg register/wrap branch vanishes
//             (MLP2, nk=48; requires nk % 3 == 0)
// EPI bits: 1=+bias, 2=gelu, 4=+residual(fp32), 32=half out (else fp32)
// =========================================================================
struct PH {
    const __half* A; const __half* B; void* C;
    const float* bias; const float* R;
    int lda, ldb, ldc, ldr;
    int nk;         // K / 64 (used when NKT==0; must be divisible by 3)
};

template<int EPI, int NKT>
__global__ __launch_bounds__(256, 2) void gemmh(PH p){
    constexpr int S = 3;
    constexpr int ABYTES = 128*128;           // 16384
    constexpr int STAGE  = 2*ABYTES;          // 32768
    constexpr int NT = 4, MT = 4;

    extern __shared__ char sm[];
    const uint32_t smb = smem_u32(sm);
    const int tid  = threadIdx.x;
    const int lane = tid & 31;
    const int warp = tid >> 5;
    const int wm   = warp >> 2;
    const int wn   = warp & 3;

    const __half* Ag = p.A + (long)blockIdx.y * 128 * p.lda;
    const __half* Bg = p.B + (long)blockIdx.x * 128 * p.ldb;

    float acc[MT][NT][4];
    #pragma unroll
    for(int i=0;i<MT;i++)
        #pragma unroll
        for(int j=0;j<NT;j++){
            acc[i][j][0]=0.f; acc[i][j][1]=0.f; acc[i][j][2]=0.f; acc[i][j][3]=0.f;
        }

    auto load_stage = [&](int kt, int s){
        const uint32_t ab = smb + s*STAGE;
        #pragma unroll
        for(int t=0;t<4;t++){
            int i = tid + t*256, row = i>>3;
            uint32_t u = (uint32_t)(i&7);
            cpa16(ab + (uint32_t)row*128 + (u ^ ((uint32_t)row&7))*16,
                  Ag + (long)row*p.lda + kt*64 + u*8);
        }
        const uint32_t bb = ab + ABYTES;
        #pragma unroll
        for(int t=0;t<4;t++){
            int i = tid + t*256, row = i>>3;
            uint32_t u = (uint32_t)(i&7);
            cpa16(bb + (uint32_t)row*128 + (u ^ ((uint32_t)row&7))*16,
                  Bg + (long)row*p.ldb + kt*64 + u*8);
        }
    };

    auto body = [&](int kt, int stg, int nk){
        cpa_wait<S-2>();
        __syncthreads();
        const uint32_t ab = smb + stg*STAGE;
        const uint32_t bb = ab + ABYTES;

        #pragma unroll
        for(int ks=0; ks<4; ks++){
            uint32_t af[MT][4], bf[NT][2];
            #pragma unroll
            for(int mt=0; mt<MT; mt++){
                uint32_t row = (uint32_t)(wm*64 + mt*16 + ((lane>>3)&1)*8 + (lane&7));
                uint32_t u   = (uint32_t)(ks*2 + (lane>>4));
                ldsm4(af[mt], ab + row*128 + (u ^ (row&7))*16);
            }
            #pragma unroll
            for(int j=0; j<NT/2; j++){
                uint32_t n = (uint32_t)(wn*32 + j*16 + ((lane>>4)&1)*8 + (lane&7));
                uint32_t u = (uint32_t)(ks*2 + ((lane>>3)&1));
                uint32_t r4[4];
                ldsm4(r4, bb + n*128 + (u ^ (n&7))*16);
                bf[2*j][0]=r4[0]; bf[2*j][1]=r4[1]; bf[2*j+1][0]=r4[2]; bf[2*j+1][1]=r4[3];
            }
            #pragma unroll
            for(int mt=0; mt<MT; mt++)
                #pragma unroll
                for(int nt=0; nt<NT; nt++)
                    mma_f16(acc[mt][nt], af[mt], bf[nt]);
        }

        const int nx = kt + S - 1;
        if(nx < nk) load_stage(nx, nx % S);
        cpa_commit();
    };

    if constexpr (NKT > 0){
        #pragma unroll
        for(int s=0;s<S-1;s++){
            if(s < NKT) load_stage(s, s);
            cpa_commit();
        }
        #pragma unroll
        for(int kt = 0; kt < NKT; kt++)
            body(kt, kt % S, NKT);
    } else {
        const int nk = p.nk;           // divisible by 3
        load_stage(0, 0); cpa_commit();
        load_stage(1, 1); cpa_commit();
        for(int kt = 0; kt < nk; kt += 3){
            body(kt,     0, nk);
            body(kt + 1, 1, nk);
            body(kt + 2, 2, nk);
        }
    }

    // ---------------- epilogue ----------------
    const long crow0 = (long)blockIdx.y*128*p.ldc + (long)blockIdx.x*128;
    const float* Rg = nullptr;
    if(EPI & 4)
        Rg = p.R + (long)blockIdx.y*128*p.ldr + (long)blockIdx.x*128;

    #pragma unroll
    for(int mt=0; mt<MT; mt++){
        #pragma unroll
        for(int nt=0; nt<NT; nt++){
            const int col = wn*32 + nt*8 + 2*(lane&3);
            #pragma unroll
            for(int hh=0; hh<2; hh++){
                const int row = wm*64 + mt*16 + (lane>>2) + hh*8;
                float v0 = acc[mt][nt][hh*2], v1 = acc[mt][nt][hh*2+1];
                if(EPI & 1){
                    float2 bb = *(const float2*)&p.bias[blockIdx.x*128 + col];
                    v0 += bb.x; v1 += bb.y;
                }
                if(EPI & 2){ v0 = gelu_exact(v0); v1 = gelu_exact(v1); }
                if(EPI & 4){
                    float2 rv = *(const float2*)(Rg + (long)row*p.ldr + col);
                    v0 += rv.x; v1 += rv.y;
                }
                if(EPI & 32){
                    __half2* Ch = (__half2*)((__half*)p.C + crow0 + (long)row*p.ldc + col);
                    *Ch = __floats2half2_rn(v0, v1);
                }else{
                    float* Cf = (float*)p.C + crow0 + (long)row*p.ldc + col;
                    *(float2*)Cf = make_float2(v0, v1);
                }
            }
        }
    }
}

// =========================================================================
// Fused flash attention, 64-key blocks, 2 CTAs/SM (round-14, unchanged)
// =========================================================================
__global__ __launch_bounds__(256, 2) void flash(
    const __half* __restrict__ qkv, const float* __restrict__ xres,
    float* __restrict__ out)
{
    extern __shared__ char sm[];
    const uint32_t smb = smem_u32(sm);
    const uint32_t qs  = smb;
    const int tid = threadIdx.x, lane = tid & 31, warp = tid >> 5;
    const int z = blockIdx.y, zb = z / NHEADS, zh = z % NHEADS;
    const long grow0 = (long)zb*SEQ + (long)blockIdx.x*128;

    const __half* Qg = qkv + grow0*QKVN + zh*HDIM;
    const __half* Kg = qkv + (long)zb*SEQ*QKVN + DIMM   + zh*HDIM;
    const __half* Vg = qkv + (long)zb*SEQ*QKVN + 2*DIMM + zh*HDIM;

    auto ldq = [&](uint32_t dst, const __half* src){
        #pragma unroll
        for(int t=0;t<4;t++){
            int i = tid + t*256, row = i>>3;
            uint32_t u = (uint32_t)(i&7);
            cpa16(dst + (uint32_t)row*128 + (u ^ ((uint32_t)row&7))*16,
                  src + (long)row*QKVN + u*8);
        }
    };
    auto ld64 = [&](uint32_t dst, const __half* src){
        #pragma unroll
        for(int t=0;t<2;t++){
            int i = tid + t*256, row = i>>3;
            uint32_t u = (uint32_t)(i&7);
            cpa16(dst + (uint32_t)row*128 + (u ^ ((uint32_t)row&7))*16,
                  src + (long)row*QKVN + u*8);
        }
    };

    ldq(qs, Qg);                                             cpa_commit();
    ld64(smb+16384, Kg);            ld64(smb+24576, Vg);            cpa_commit();
    ld64(smb+32768, Kg + 64l*QKVN); ld64(smb+40960, Vg + 64l*QKVN); cpa_commit();

    cpa_wait<2>();
    __syncthreads();

    uint32_t qf[4][4];
    #pragma unroll
    for(int ks=0; ks<4; ks++){
        uint32_t row = (uint32_t)(warp*16 + ((lane>>3)&1)*8 + (lane&7));
        uint32_t u   = (uint32_t)(2*ks + (lane>>4));
        ldsm4(qf[ks], qs + row*128 + (u ^ (row&7))*16);
    }

    float m0 = -1e30f, m1 = -1e30f, l0 = 0.f, l1 = 0.f;
    float o[8][4];
    #pragma unroll
    for(int nt=0;nt<8;nt++){ o[nt][0]=0.f; o[nt][1]=0.f; o[nt][2]=0.f; o[nt][3]=0.f; }

    for(int kb=0; kb<8; kb++){
        if(kb < 6) cpa_wait<1>(); else cpa_wait<0>();
        __syncthreads();
        const uint32_t kbuf = smb + 16384 + (uint32_t)(kb&1)*16384;
        const uint32_t vbuf = kbuf + 8192;

        float s[8][4];
        #pragma unroll
        for(int nt=0;nt<8;nt++){ s[nt][0]=0.f; s[nt][1]=0.f; s[nt][2]=0.f; s[nt][3]=0.f; }
        #pragma unroll
        for(int ks=0; ks<4; ks++){
            #pragma unroll
            for(int j=0;j<4;j++){
                uint32_t n = (uint32_t)(j*16 + ((lane>>4)&1)*8 + (lane&7));
                uint32_t u = (uint32_t)(2*ks + ((lane>>3)&1));
                uint32_t r4[4];
                ldsm4(r4, kbuf + n*128 + (u ^ (n&7))*16);
                mma_f16(s[2*j  ], qf[ks], r4    );
                mma_f16(s[2*j+1], qf[ks], r4 + 2);
            }
        }

        float cm0 = -1e30f, cm1 = -1e30f;
        #pragma unroll
        for(int nt=0;nt<8;nt++){
            s[nt][0]*=0.125f; s[nt][1]*=0.125f; s[nt][2]*=0.125f; s[nt][3]*=0.125f;
            cm0 = fmaxf(cm0, fmaxf(s[nt][0], s[nt][1]));
            cm1 = fmaxf(cm1, fmaxf(s[nt][2], s[nt][3]));
        }
        cm0 = fmaxf(cm0, __shfl_xor_sync(~0u,cm0,1));
        cm0 = fmaxf(cm0, __shfl_xor_sync(~0u,cm0,2));
        cm1 = fmaxf(cm1, __shfl_xor_sync(~0u,cm1,1));
        cm1 = fmaxf(cm1, __shfl_xor_sync(~0u,cm1,2));
        const float mn0 = fmaxf(m0, cm0), mn1 = fmaxf(m1, cm1);
        const float sf0 = __expf(m0 - mn0), sf1 = __expf(m1 - mn1);
        float sum0 = 0.f, sum1 = 0.f;
        #pragma unroll
        for(int nt=0;nt<8;nt++){
            s[nt][0] = __expf(s[nt][0]-mn0); s[nt][1] = __expf(s[nt][1]-mn0);
            s[nt][2] = __expf(s[nt][2]-mn1); s[nt][3] = __expf(s[nt][3]-mn1);
            sum0 += s[nt][0] + s[nt][1];
            sum1 += s[nt][2] + s[nt][3];
        }
        sum0 += __shfl_xor_sync(~0u,sum0,1); sum0 += __shfl_xor_sync(~0u,sum0,2);
        sum1 += __shfl_xor_sync(~0u,sum1,1); sum1 += __shfl_xor_sync(~0u,sum1,2);
        l0 = l0*sf0 + sum0; l1 = l1*sf1 + sum1;
        m0 = mn0; m1 = mn1;
        #pragma unroll
        for(int nt=0;nt<8;nt++){
            o[nt][0]*=sf0; o[nt][1]*=sf0; o[nt][2]*=sf1; o[nt][3]*=sf1;
        }

        #pragma unroll
        for(int kk=0; kk<4; kk++){
            uint32_t pa[4];
            pa[0] = packh2(s[2*kk  ][0], s[2*kk  ][1]);
            pa[1] = packh2(s[2*kk  ][2], s[2*kk  ][3]);
            pa[2] = packh2(s[2*kk+1][0], s[2*kk+1][1]);
            pa[3] = packh2(s[2*kk+1][2], s[2*kk+1][3]);
            const int g = lane>>3, i = lane&7;
            #pragma unroll
            for(int dp=0; dp<4; dp++){
                uint32_t key = (uint32_t)(kk*16 + (g&1)*8 + i);
                uint32_t dg  = (uint32_t)(dp*2 + (g>>1));
                uint32_t r4[4];
                ldsm4t(r4, vbuf + key*128 + (dg ^ (key&7))*16);
                mma_f16(o[2*dp  ], pa, r4    );
                mma_f16(o[2*dp+1], pa, r4 + 2);
            }
        }

        __syncthreads();
        if(kb + 2 < 8){
            const uint32_t dst = smb + 16384 + (uint32_t)(kb&1)*16384;
            ld64(dst,        Kg + (long)(kb+2)*64*QKVN);
            ld64(dst + 8192, Vg + (long)(kb+2)*64*QKVN);
            cpa_commit();
        }
    }

    const float inv0 = 1.f/l0, inv1 = 1.f/l1;
    const long gr0 = grow0 + warp*16 + (lane>>2);
    const long gr1 = gr0 + 8;
    const int  col = zh*HDIM + 2*(lane&3);
    #pragma unroll
    for(int nt=0; nt<8; nt++){
        const int c = col + nt*8;
        float2 r0 = *(const float2*)&xres[gr0*DIMM + c];
        float2 r1 = *(const float2*)&xres[gr1*DIMM + c];
        *(float2*)&out[gr0*DIMM + c] = make_float2(o[nt][0]*inv0 + r0.x, o[nt][1]*inv0 + r0.y);
        *(float2*)&out[gr1*DIMM + c] = make_float2(o[nt][2]*inv1 + r1.x, o[nt][3]*inv1 + r1.y);
    }
}

// ---------------- LayerNorm, warp-per-row (round-9, unchanged) -----------------
__global__ __launch_bounds__(256) void ln_kernel(
    const float* __restrict__ x, const float* __restrict__ w,
    const float* __restrict__ b, __half* __restrict__ out)
{
    const int warp = threadIdx.x >> 5, lane = threadIdx.x & 31;
    const long row = (long)blockIdx.x*8 + warp;
    const float4* xr = (const float4*)(x + row*DIMM);

    float4 v[6];
    #pragma unroll
    for(int i=0;i<6;i++) v[i] = xr[lane + i*32];

    float s = 0.f, s2 = 0.f;
    #pragma unroll
    for(int i=0;i<6;i++){
        s  += (v[i].x + v[i].y) + (v[i].z + v[i].w);
        s2 += v[i].x*v[i].x + v[i].y*v[i].y + v[i].z*v[i].z + v[i].w*v[i].w;
    }
    #pragma unroll
    for(int o=16;o;o>>=1){
        s  += __shfl_xor_sync(~0u, s,  o);
        s2 += __shfl_xor_sync(~0u, s2, o);
    }
    const float mu  = s * (1.f/DIMM);
    const float var = s2 * (1.f/DIMM) - mu*mu;
    const float inv = rsqrtf(var + 1e-5f);

    const float4* wv = (const float4*)w;
    const float4* bv = (const float4*)b;
    uint2* orow = (uint2*)(out + row*DIMM);
    #pragma unroll
    for(int i=0;i<6;i++){
        const int c = lane + i*32;
        float4 ww = wv[c], bb = bv[c];
        uint2 pk;
        pk.x = packh2((v[i].x - mu)*inv*ww.x + bb.x, (v[i].y - mu)*inv*ww.y + bb.y);
        pk.y = packh2((v[i].z - mu)*inv*ww.z + bb.z, (v[i].w - mu)*inv*ww.w + bb.w);
        orow[c] = pk;
    }
}

// ---------------- weight transpose [K,N] fp32 -> [N,K] fp16 --------------------
__global__ void wtrans(const float* __restrict__ in, __half* __restrict__ out, int K, int N){
    __shared__ float t[32][33];
    const int k0 = blockIdx.y*32, n0 = blockIdx.x*32;
    const int tx = threadIdx.x & 31, ty = threadIdx.x >> 5;
    #pragma unroll
    for(int i=0;i<4;i++)
        t[ty+8*i][tx] = in[(size_t)(k0+ty+8*i)*N + n0+tx];
    __syncthreads();
    #pragma unroll
    for(int i=0;i<4;i++)
        out[(size_t)(n0+ty+8*i)*K + k0+tx] = __float2half_rn(t[tx][ty+8*i]);
}

__global__ void concat_bias(const float* a, const float* b, const float* c, float* o){
    int i = blockIdx.x*256 + threadIdx.x;
    if(i < DIMM){ o[i] = a[i]; o[i+DIMM] = b[i]; o[i+2*DIMM] = c[i]; }
}

// ---------------- host ----------------
static PH mkph(const __half* A, const __half* B, void* C, const float* bias,
               const float* R, int lda, int ldb, int ldc, int ldr, int nk){
    PH p{};
    p.A=A; p.B=B; p.C=C; p.bias=bias; p.R=R;
    p.lda=lda; p.ldb=ldb; p.ldc=ldc; p.ldr=ldr;
    p.nk=nk;
    return p;
}

extern "C" void kernel_launch(void* const* d_in, const int* in_sizes, int n_in,
                              void* d_out, int out_size){
    const float* x    = (const float*)d_in[0];
    const float* ln_w = (const float*)d_in[1];
    const float* ln_b = (const float*)d_in[2];
    const float* wq   = (const float*)d_in[3];
    const float* bq   = (const float*)d_in[4];
    const float* wk   = (const float*)d_in[5];
    const float* bk   = (const float*)d_in[6];
    const float* wv   = (const float*)d_in[7];
    const float* bv   = (const float*)d_in[8];
    const float* w1   = (const float*)d_in[9];
    const float* b1   = (const float*)d_in[10];
    const float* w2   = (const float*)d_in[11];
    const float* b2   = (const float*)d_in[12];

    float *px, *px2, *pbqkv;
    __half *pln, *pqkv, *phid, *pwqkvT, *pw1T, *pw2T;
    cudaGetSymbolAddress((void**)&px    , g_x   );
    cudaGetSymbolAddress((void**)&px2   , g_x2  );
    cudaGetSymbolAddress((void**)&pbqkv , g_bqkv);
    cudaGetSymbolAddress((void**)&pln   , h_ln  );
    cudaGetSymbolAddress((void**)&pqkv  , h_qkv );
    cudaGetSymbolAddress((void**)&phid  , h_hid );
    cudaGetSymbolAddress((void**)&pwqkvT, h_wqkvT);
    cudaGetSymbolAddress((void**)&pw1T  , h_w1T );
    cudaGetSymbolAddress((void**)&pw2T  , h_w2T );

    const int SMG  = 3*32768;                // 98304 (2 CTAs/SM = 192KB)
    const int SMFL = 16384 + 2*16384;        // 49152 (2 CTAs/SM = 96KB)
    cudaFuncSetAttribute(gemmh<33,12>, cudaFuncAttributeMaxDynamicSharedMemorySize, SMG);
    cudaFuncSetAttribute(gemmh<35,12>, cudaFuncAttributeMaxDynamicSharedMemorySize, SMG);
    cudaFuncSetAttribute(gemmh< 5, 0>, cudaFuncAttributeMaxDynamicSharedMemorySize, SMG);
    cudaFuncSetAttribute(flash,        cudaFuncAttributeMaxDynamicSharedMemorySize, SMFL);

    // weight prep (amortized over 12 layers)
    wtrans<<<dim3(DIMM/32, DIMM/32), 256>>>(wq, pwqkvT,                       DIMM, DIMM);
    wtrans<<<dim3(DIMM/32, DIMM/32), 256>>>(wk, pwqkvT + (size_t)DIMM*DIMM,   DIMM, DIMM);
    wtrans<<<dim3(DIMM/32, DIMM/32), 256>>>(wv, pwqkvT + (size_t)2*DIMM*DIMM, DIMM, DIMM);
    wtrans<<<dim3(MLPD/32, DIMM/32), 256>>>(w1, pw1T, DIMM, MLPD);
    wtrans<<<dim3(DIMM/32, MLPD/32), 256>>>(w2, pw2T, MLPD, DIMM);
    concat_bias<<<3, 256>>>(bq, bk, bv, pbqkv);

    // residual stream: layer 0 reads the harness input directly (no copy);
    // layer 11's MLP2 writes d_out directly (no final copy).
    const float* cur = x;

    for(int l=0; l<NDEPTH; l++){
        // --- attention block ---
        ln_kernel<<<MROWS/8, 256>>>(cur, ln_w, ln_b, pln);

        // fused QKV: [8192,2304] ; bias, half out  (nk=12 compile-time)
        { PH p = mkph(pln, pwqkvT, pqkv, pbqkv, nullptr, DIMM, DIMM, QKVN, 0, DIMM/64);
          gemmh<33,12><<<dim3(QKVN/128, MROWS/128, 1), 256, SMG>>>(p); }

        // fused attention: x2 = softmax(QK^T/8)V + cur
        flash<<<dim3(SEQ/128, NZ), 256, SMFL>>>(pqkv, cur, px2);

        // --- MLP block ---
        ln_kernel<<<MROWS/8, 256>>>(px2, ln_w, ln_b, pln);

        { PH p = mkph(pln, pw1T, phid, b1, nullptr, DIMM, DIMM, MLPD, 0, DIMM/64);
          gemmh<35,12><<<dim3(MLPD/128, MROWS/128, 1), 256, SMG>>>(p); }  // bias+gelu+half

        float* dst = (l == NDEPTH-1) ? (float*)d_out : px;
        { PH p = mkph(phid, pw2T, dst, b2, px2, MLPD, MLPD, DIMM, DIMM, MLPD/64);
          gemmh<5,0><<<dim3(DIMM/128, MROWS/128, 1), 256, SMG>>>(p); }    // bias+resid fp32 (nk=48, unroll-by-3)
        cur = dst;
    }
}